// round 5
// baseline (speedup 1.0000x reference)
#include <cuda_runtime.h>
#include <cuda_bf16.h>
#include <cstdint>
#include <math.h>

// Problem constants
#define Bz   4
#define S1z  1024
#define S2z  1024
#define Dz   1024
#define Hz   16
#define DKz  64
#define FFNz 4096

// ---------------- scratch ----------------
__device__ float g_y  [Bz * S1z * Dz];
__device__ float g_kvn[Bz * S2z * Dz];
__device__ float g_q  [Bz * S1z * Dz];
__device__ float g_k  [Bz * S2z * Dz];
__device__ float g_v  [Bz * S2z * Dz];
__device__ float g_o  [Bz * S1z * Dz];
__device__ float g_x2 [Bz * S1z * Dz];
__device__ float g_h  [Bz * S1z * FFNz];
__device__ float g_wt [16 * 1024 * 1024];   // transposed weights

// ---------------- helpers ----------------
__device__ __forceinline__ uint32_t smem_u32(const void* p) {
    return (uint32_t)__cvta_generic_to_shared(p);
}
__device__ __forceinline__ void cp16(uint32_t dst, const void* src) {
    asm volatile("cp.async.cg.shared.global [%0], [%1], 16;" :: "r"(dst), "l"(src));
}
__device__ __forceinline__ void mma_tf32(float* c, const uint32_t* a, const uint32_t* b) {
    asm volatile("mma.sync.aligned.m16n8k8.row.col.f32.tf32.tf32.f32 "
                 "{%0,%1,%2,%3},{%4,%5,%6,%7},{%8,%9},{%0,%1,%2,%3};"
                 : "+f"(c[0]), "+f"(c[1]), "+f"(c[2]), "+f"(c[3])
                 : "r"(a[0]), "r"(a[1]), "r"(a[2]), "r"(a[3]), "r"(b[0]), "r"(b[1]));
}
__device__ __forceinline__ void ldsm4(uint32_t* r, uint32_t addr) {
    asm volatile("ldmatrix.sync.aligned.m8n8.x4.shared.b16 {%0,%1,%2,%3}, [%4];"
                 : "=r"(r[0]), "=r"(r[1]), "=r"(r[2]), "=r"(r[3]) : "r"(addr));
}

// ---------------- tf32 tensor-core GEMM (LDSM fragment feed) -----------------
// C[M,N] = A[M,K] @ Bt^T, both A [M,K] and Bt [N,K] row-major (K contiguous).
// Tile 128x128, BK=16, 8 warps (warp: WM=32 x WN=64 -> MI=2, NJ=8).
// 3-stage cp.async ring, one barrier per chunk. Fragments via ldmatrix.x4.b16.
#define GSTR 20              // floats per SMEM row (16 + 4 pad)
#define GEMM_SMEM (3 * 2 * 128 * GSTR * 4)   // 3 stages x (A+B) x 128 rows

__global__ void __launch_bounds__(256)
tgemm(int K,
      const float* __restrict__ A, int lda,
      const float* __restrict__ Bt, int ldb,
      float* __restrict__ C, int ldc,
      const float* __restrict__ bias,
      const float* __restrict__ res, int ldres, int relu)
{
    extern __shared__ __align__(16) float sm[];
    // layout: stage s: A rows [s*256 .. s*256+128), B rows [s*256+128 ..)
    int tid = threadIdx.x;
    int bm = blockIdx.y * 128, bn = blockIdx.x * 128;
    int warp = tid >> 5, lane = tid & 31, g = lane >> 2, tg = lane & 3;
    int wn = warp & 1, wm = warp >> 1;          // 4x2 warp grid: WM=32, WN=64

    uint32_t sb = smem_u32(sm);
    const int NT = K / 16;

    auto issue = [&](int t) {
        uint32_t base = sb + (uint32_t)((t % 3) * 256 * GSTR) * 4u;
        #pragma unroll
        for (int i = 0; i < 2; i++) {           // A: 128 rows x 16 floats
            int e = tid + i * 256, r = e >> 2, c = (e & 3) * 4;
            cp16(base + (uint32_t)(r * GSTR + c) * 4u,
                 A + (size_t)(bm + r) * lda + t * 16 + c);
        }
        #pragma unroll
        for (int i = 0; i < 2; i++) {           // B: 128 rows x 16 floats
            int e = tid + i * 256, r = e >> 2, c = (e & 3) * 4;
            cp16(base + (uint32_t)((128 + r) * GSTR + c) * 4u,
                 Bt + (size_t)(bn + r) * ldb + t * 16 + c);
        }
        asm volatile("cp.async.commit_group;");
    };

    // per-lane ldmatrix byte offsets within a stage
    int q = lane >> 3, rr = lane & 7;
    // A frag (mi, ks): row = wm*32 + mi*16 + (q&1)*8 + rr ; col = ks*8 + (q>>1)*4
    uint32_t a_off[2][2];
    #pragma unroll
    for (int mi = 0; mi < 2; mi++)
        #pragma unroll
        for (int ks = 0; ks < 2; ks++)
            a_off[mi][ks] = (uint32_t)(((wm*32 + mi*16 + (q&1)*8 + rr) * GSTR
                                        + ks*8 + (q>>1)*4) * 4);
    // B frag pair (jp, ks): n = wn*64 + jp*16 + (q>>1)*8 + rr ; col = ks*8 + (q&1)*4
    uint32_t b_off[4][2];
    #pragma unroll
    for (int jp = 0; jp < 4; jp++)
        #pragma unroll
        for (int ks = 0; ks < 2; ks++)
            b_off[jp][ks] = (uint32_t)(((128 + wn*64 + jp*16 + (q>>1)*8 + rr) * GSTR
                                        + ks*8 + (q&1)*4) * 4);

    float acc[2][8][4] = {};

    issue(0);
    if (NT > 1) issue(1);

    for (int t = 0; t < NT; t++) {
        if (t + 1 < NT) asm volatile("cp.async.wait_group 1;");
        else            asm volatile("cp.async.wait_group 0;");
        __syncthreads();
        if (t + 2 < NT) issue(t + 2);

        uint32_t stage = sb + (uint32_t)((t % 3) * 256 * GSTR) * 4u;
        #pragma unroll
        for (int ks = 0; ks < 2; ks++) {
            uint32_t a[2][4], b[4][4];
            #pragma unroll
            for (int mi = 0; mi < 2; mi++) ldsm4(a[mi], stage + a_off[mi][ks]);
            #pragma unroll
            for (int jp = 0; jp < 4; jp++) ldsm4(b[jp], stage + b_off[jp][ks]);
            #pragma unroll
            for (int mi = 0; mi < 2; mi++)
                #pragma unroll
                for (int jp = 0; jp < 4; jp++) {
                    mma_tf32(acc[mi][jp*2],     a[mi], &b[jp][0]);
                    mma_tf32(acc[mi][jp*2 + 1], a[mi], &b[jp][2]);
                }
        }
    }

    // epilogue
    #pragma unroll
    for (int mi = 0; mi < 2; mi++) {
        #pragma unroll
        for (int j = 0; j < 8; j++) {
            int m0 = bm + wm*32 + mi*16 + g;
            int n0 = bn + wn*64 + j*8 + 2*tg;
            float v0 = acc[mi][j][0], v1 = acc[mi][j][1];
            float v2 = acc[mi][j][2], v3 = acc[mi][j][3];
            if (bias) {
                float b0 = bias[n0], b1 = bias[n0 + 1];
                v0 += b0; v1 += b1; v2 += b0; v3 += b1;
            }
            if (res) {
                v0 += res[(size_t)m0*ldres + n0];
                v1 += res[(size_t)m0*ldres + n0 + 1];
                v2 += res[(size_t)(m0 + 8)*ldres + n0];
                v3 += res[(size_t)(m0 + 8)*ldres + n0 + 1];
            }
            if (relu) {
                v0 = fmaxf(v0, 0.f); v1 = fmaxf(v1, 0.f);
                v2 = fmaxf(v2, 0.f); v3 = fmaxf(v3, 0.f);
            }
            *(float2*)&C[(size_t)m0*ldc + n0]       = make_float2(v0, v1);
            *(float2*)&C[(size_t)(m0 + 8)*ldc + n0] = make_float2(v2, v3);
        }
    }
}

// ---------------- transpose: dst[N,K] = src[K,N] -----------------------------
__global__ void transpose_kernel(const float* __restrict__ src, float* __restrict__ dst,
                                 int R, int C)
{
    __shared__ float tile[32][33];
    int tx = threadIdx.x, ty = threadIdx.y;
    int c0 = blockIdx.x * 32, r0 = blockIdx.y * 32;
    #pragma unroll
    for (int j = 0; j < 32; j += 8)
        tile[ty + j][tx] = src[(size_t)(r0 + ty + j) * C + c0 + tx];
    __syncthreads();
    #pragma unroll
    for (int j = 0; j < 32; j += 8)
        dst[(size_t)(c0 + ty + j) * R + r0 + tx] = tile[tx][ty + j];
}

// ---------------- LayerNorm ----------------
__global__ void ln_kernel(const float* __restrict__ in, float* __restrict__ out,
                          const float* __restrict__ g, const float* __restrict__ bta)
{
    size_t row = blockIdx.x;
    int tid = threadIdx.x;
    const float4* xp = (const float4*)(in + row * (size_t)Dz);
    float4 v = xp[tid];
    float s = v.x + v.y + v.z + v.w;
    float q = v.x*v.x + v.y*v.y + v.z*v.z + v.w*v.w;
    #pragma unroll
    for (int o = 16; o; o >>= 1) {
        s += __shfl_xor_sync(0xffffffffu, s, o);
        q += __shfl_xor_sync(0xffffffffu, q, o);
    }
    __shared__ float ss[8], qq[8];
    int lane = tid & 31, wid = tid >> 5;
    if (!lane) { ss[wid] = s; qq[wid] = q; }
    __syncthreads();
    if (tid < 32) {
        s = (tid < 8) ? ss[tid] : 0.f;
        q = (tid < 8) ? qq[tid] : 0.f;
        #pragma unroll
        for (int o = 4; o; o >>= 1) {
            s += __shfl_xor_sync(0xffffffffu, s, o);
            q += __shfl_xor_sync(0xffffffffu, q, o);
        }
        if (!tid) { ss[0] = s; qq[0] = q; }
    }
    __syncthreads();
    float mean = ss[0] * (1.f / Dz);
    float var  = qq[0] * (1.f / Dz) - mean * mean;
    float inv  = rsqrtf(var + 1e-5f);
    float4 gv = ((const float4*)g)[tid];
    float4 bv = ((const float4*)bta)[tid];
    float4 o4;
    o4.x = (v.x - mean) * inv * gv.x + bv.x;
    o4.y = (v.y - mean) * inv * gv.y + bv.y;
    o4.z = (v.z - mean) * inv * gv.z + bv.z;
    o4.w = (v.w - mean) * inv * gv.w + bv.w;
    ((float4*)(out + row * (size_t)Dz))[tid] = o4;
}

// ---------------- elementwise add ----------------
__global__ void add_kernel(const float* __restrict__ a, const float* __restrict__ b,
                           float* __restrict__ c)
{
    int i = blockIdx.x * blockDim.x + threadIdx.x;
    float4 av = ((const float4*)a)[i];
    float4 bv = ((const float4*)b)[i];
    float4 cv;
    cv.x = av.x + bv.x; cv.y = av.y + bv.y; cv.z = av.z + bv.z; cv.w = av.w + bv.w;
    ((float4*)c)[i] = cv;
}

// ---------------- fused flash cross-attention --------------------------------
#define KSTR 68
#define VSTR 72
#define PSTR 68
#define FLASH_SMEM ((2*64*KSTR + 2*64*VSTR + 128*PSTR + S2z) * 4)

__global__ void __launch_bounds__(256)
flash_kernel(const float* __restrict__ Q, const float* __restrict__ Kg,
             const float* __restrict__ Vg, const int* __restrict__ mask,
             float* __restrict__ O)
{
    extern __shared__ float sm[];
    float* Ks = sm;
    float* Vs = Ks + 2*64*KSTR;
    float* Ps = Vs + 2*64*VSTR;
    float* Mf = Ps + 128*PSTR;

    int bh = blockIdx.y;
    int b = bh / Hz, h = bh % Hz;
    int q0 = blockIdx.x * 128;
    int tid = threadIdx.x, warp = tid >> 5, lane = tid & 31, g = lane >> 2, tg = lane & 3;

    const float* Qb = Q  + ((size_t)(b*S1z + q0))*Dz + h*DKz;
    const float* Kb = Kg + ((size_t)b*S2z)*Dz + h*DKz;
    const float* Vb = Vg + ((size_t)b*S2z)*Dz + h*DKz;

    for (int i = tid; i < S2z; i += 256) Mf[i] = mask[(size_t)b*S2z + i] ? 1.f : 0.f;

    uint32_t qa[8][4];
    {
        int ml = warp*16 + g, mh = ml + 8;
        #pragma unroll
        for (int ki = 0; ki < 8; ki++) {
            qa[ki][0] = __float_as_uint(Qb[(size_t)ml*Dz + ki*8 + tg]);
            qa[ki][1] = __float_as_uint(Qb[(size_t)mh*Dz + ki*8 + tg]);
            qa[ki][2] = __float_as_uint(Qb[(size_t)ml*Dz + ki*8 + tg + 4]);
            qa[ki][3] = __float_as_uint(Qb[(size_t)mh*Dz + ki*8 + tg + 4]);
        }
    }

    uint32_t ksb = smem_u32(Ks);
    uint32_t vsb = smem_u32(Vs);

    auto issue = [&](int t) {
        int buf = t & 1;
        #pragma unroll
        for (int i = 0; i < 4; i++) {
            int e = tid + i*256;
            int r = e >> 4, c = (e & 15) * 4;
            cp16(ksb + (uint32_t)(buf*64*KSTR + r*KSTR + c)*4u,
                 Kb + (size_t)(t*64 + r)*Dz + c);
            cp16(vsb + (uint32_t)(buf*64*VSTR + r*VSTR + c)*4u,
                 Vb + (size_t)(t*64 + r)*Dz + c);
        }
        asm volatile("cp.async.commit_group;");
    };

    float s_acc[8][4];
    float o_acc[8][4] = {};
    float m_lo = -INFINITY, m_hi = -INFINITY, l_lo = 0.f, l_hi = 0.f;
    int rl = warp*16 + g, rh = rl + 8;

    issue(0);
    for (int t = 0; t < S2z/64; t++) {
        if (t + 1 < S2z/64) { issue(t + 1); asm volatile("cp.async.wait_group 1;"); }
        else                { asm volatile("cp.async.wait_group 0;"); }
        __syncthreads();
        int buf = t & 1;
        const float* kp = Ks + buf*64*KSTR;
        const float* vp = Vs + buf*64*VSTR;

        #pragma unroll
        for (int j = 0; j < 8; j++)
            s_acc[j][0] = s_acc[j][1] = s_acc[j][2] = s_acc[j][3] = 0.f;
        #pragma unroll
        for (int ki = 0; ki < 8; ki++) {
            #pragma unroll
            for (int j = 0; j < 8; j++) {
                int n0 = j*8 + g;
                uint32_t bb[2] = {
                    __float_as_uint(kp[n0*KSTR + ki*8 + tg]),
                    __float_as_uint(kp[n0*KSTR + ki*8 + tg + 4]) };
                mma_tf32(s_acc[j], qa[ki], bb);
            }
        }

        float rmax_lo = -INFINITY, rmax_hi = -INFINITY;
        #pragma unroll
        for (int j = 0; j < 8; j++) {
            int c0 = t*64 + j*8 + 2*tg;
            float mf0 = Mf[c0], mf1 = Mf[c0 + 1];
            s_acc[j][0] = (mf0 != 0.f) ? s_acc[j][0]*0.125f : -1e9f;
            s_acc[j][1] = (mf1 != 0.f) ? s_acc[j][1]*0.125f : -1e9f;
            s_acc[j][2] = (mf0 != 0.f) ? s_acc[j][2]*0.125f : -1e9f;
            s_acc[j][3] = (mf1 != 0.f) ? s_acc[j][3]*0.125f : -1e9f;
            rmax_lo = fmaxf(rmax_lo, fmaxf(s_acc[j][0], s_acc[j][1]));
            rmax_hi = fmaxf(rmax_hi, fmaxf(s_acc[j][2], s_acc[j][3]));
        }
        rmax_lo = fmaxf(rmax_lo, __shfl_xor_sync(0xffffffffu, rmax_lo, 1));
        rmax_lo = fmaxf(rmax_lo, __shfl_xor_sync(0xffffffffu, rmax_lo, 2));
        rmax_hi = fmaxf(rmax_hi, __shfl_xor_sync(0xffffffffu, rmax_hi, 1));
        rmax_hi = fmaxf(rmax_hi, __shfl_xor_sync(0xffffffffu, rmax_hi, 2));
        float mn_lo = fmaxf(m_lo, rmax_lo), mn_hi = fmaxf(m_hi, rmax_hi);
        float al_lo = __expf(m_lo - mn_lo), al_hi = __expf(m_hi - mn_hi);
        m_lo = mn_lo; m_hi = mn_hi;

        float sum_lo = 0.f, sum_hi = 0.f;
        #pragma unroll
        for (int j = 0; j < 8; j++) {
            float p0 = __expf(s_acc[j][0] - mn_lo);
            float p1 = __expf(s_acc[j][1] - mn_lo);
            float p2 = __expf(s_acc[j][2] - mn_hi);
            float p3 = __expf(s_acc[j][3] - mn_hi);
            sum_lo += p0 + p1; sum_hi += p2 + p3;
            int c = j*8 + 2*tg;
            *(float2*)&Ps[rl*PSTR + c] = make_float2(p0, p1);
            *(float2*)&Ps[rh*PSTR + c] = make_float2(p2, p3);
        }
        sum_lo += __shfl_xor_sync(0xffffffffu, sum_lo, 1);
        sum_lo += __shfl_xor_sync(0xffffffffu, sum_lo, 2);
        sum_hi += __shfl_xor_sync(0xffffffffu, sum_hi, 1);
        sum_hi += __shfl_xor_sync(0xffffffffu, sum_hi, 2);
        l_lo = al_lo*l_lo + sum_lo;
        l_hi = al_hi*l_hi + sum_hi;
        #pragma unroll
        for (int j = 0; j < 8; j++) {
            o_acc[j][0] *= al_lo; o_acc[j][1] *= al_lo;
            o_acc[j][2] *= al_hi; o_acc[j][3] *= al_hi;
        }
        __syncwarp();

        #pragma unroll
        for (int ki = 0; ki < 8; ki++) {
            int k0 = ki*8 + tg;
            uint32_t pa[4];
            pa[0] = __float_as_uint(Ps[rl*PSTR + k0]);
            pa[1] = __float_as_uint(Ps[rh*PSTR + k0]);
            pa[2] = __float_as_uint(Ps[rl*PSTR + k0 + 4]);
            pa[3] = __float_as_uint(Ps[rh*PSTR + k0 + 4]);
            #pragma unroll
            for (int j = 0; j < 8; j++) {
                int n0 = j*8 + g;
                uint32_t bb[2] = {
                    __float_as_uint(vp[(ki*8 + tg    )*VSTR + n0]),
                    __float_as_uint(vp[(ki*8 + tg + 4)*VSTR + n0]) };
                mma_tf32(o_acc[j], pa, bb);
            }
        }
        __syncthreads();
    }

    float il_lo = 1.f / l_lo, il_hi = 1.f / l_hi;
    float* Ob = O + ((size_t)(b*S1z + q0))*Dz + h*DKz;
    #pragma unroll
    for (int j = 0; j < 8; j++) {
        int c = j*8 + 2*tg;
        *(float2*)&Ob[(size_t)rl*Dz + c] =
            make_float2(o_acc[j][0]*il_lo, o_acc[j][1]*il_lo);
        *(float2*)&Ob[(size_t)rh*Dz + c] =
            make_float2(o_acc[j][2]*il_hi, o_acc[j][3]*il_hi);
    }
}

// ---------------- host orchestration ----------------
extern "C" void kernel_launch(void* const* d_in, const int* in_sizes, int n_in,
                              void* d_out, int out_size)
{
    const float* x     = (const float*)d_in[0];
    const float* kv    = (const float*)d_in[1];
    const int*   mask  = (const int*)  d_in[2];
    const float* ln1_g = (const float*)d_in[3];
    const float* ln1_b = (const float*)d_in[4];
    const float* qw[2] = { (const float*)d_in[5],  (const float*)d_in[10] };
    const float* kw[2] = { (const float*)d_in[6],  (const float*)d_in[11] };
    const float* vw[2] = { (const float*)d_in[7],  (const float*)d_in[12] };
    const float* ow[2] = { (const float*)d_in[8],  (const float*)d_in[13] };
    const float* ob[2] = { (const float*)d_in[9],  (const float*)d_in[14] };
    const float* ln2_g = (const float*)d_in[15];
    const float* ln2_b = (const float*)d_in[16];
    const float* w1    = (const float*)d_in[17];
    const float* b1    = (const float*)d_in[18];
    const float* w2    = (const float*)d_in[19];
    const float* b2    = (const float*)d_in[20];
    float* out = (float*)d_out;

    float *y, *kvn, *q, *k, *v, *o, *x2, *hbuf, *wt;
    cudaGetSymbolAddress((void**)&y,    g_y);
    cudaGetSymbolAddress((void**)&kvn,  g_kvn);
    cudaGetSymbolAddress((void**)&q,    g_q);
    cudaGetSymbolAddress((void**)&k,    g_k);
    cudaGetSymbolAddress((void**)&v,    g_v);
    cudaGetSymbolAddress((void**)&o,    g_o);
    cudaGetSymbolAddress((void**)&x2,   g_x2);
    cudaGetSymbolAddress((void**)&hbuf, g_h);
    cudaGetSymbolAddress((void**)&wt,   g_wt);

    cudaFuncSetAttribute(flash_kernel,
        cudaFuncAttributeMaxDynamicSharedMemorySize, FLASH_SMEM);
    cudaFuncSetAttribute(tgemm,
        cudaFuncAttributeMaxDynamicSharedMemorySize, GEMM_SMEM);

    const int M = Bz * S1z;   // 4096
    const size_t MM = 1024 * 1024;

    float* qwt[2] = { wt + 0*MM, wt + 4*MM };
    float* kwt[2] = { wt + 1*MM, wt + 5*MM };
    float* vwt[2] = { wt + 2*MM, wt + 6*MM };
    float* owt[2] = { wt + 3*MM, wt + 7*MM };
    float* w1t = wt + 8*MM;    // [4096,1024]
    float* w2t = wt + 12*MM;   // [1024,4096]

    dim3 tb(32, 8);
    for (int l = 0; l < 2; l++) {
        transpose_kernel<<<dim3(32,32), tb>>>(qw[l], qwt[l], Dz, Dz);
        transpose_kernel<<<dim3(32,32), tb>>>(kw[l], kwt[l], Dz, Dz);
        transpose_kernel<<<dim3(32,32), tb>>>(vw[l], vwt[l], Dz, Dz);
        transpose_kernel<<<dim3(32,32), tb>>>(ow[l], owt[l], Dz, Dz);
    }
    transpose_kernel<<<dim3(FFNz/32, Dz/32), tb>>>(w1, w1t, Dz, FFNz);
    transpose_kernel<<<dim3(Dz/32, FFNz/32), tb>>>(w2, w2t, FFNz, Dz);

    ln_kernel<<<Bz * S1z, 256>>>(x,  y,   ln1_g, ln1_b);
    ln_kernel<<<Bz * S2z, 256>>>(kv, kvn, ln1_g, ln1_b);

    dim3 gProj(Dz/128, M/128);      // (8, 32)
    dim3 gFlash(S1z/128, Bz*Hz);    // (8, 64)
    dim3 gF1(FFNz/128, M/128);      // (32, 32)

    for (int l = 0; l < 2; l++) {
        tgemm<<<gProj, 256, GEMM_SMEM>>>(Dz, y,   Dz, qwt[l], Dz, q, Dz,
            nullptr, nullptr, 0, 0);
        tgemm<<<gProj, 256, GEMM_SMEM>>>(Dz, kvn, Dz, kwt[l], Dz, k, Dz,
            nullptr, nullptr, 0, 0);
        tgemm<<<gProj, 256, GEMM_SMEM>>>(Dz, kvn, Dz, vwt[l], Dz, v, Dz,
            nullptr, nullptr, 0, 0);

        flash_kernel<<<gFlash, 256, FLASH_SMEM>>>(q, k, v, mask, o);

        tgemm<<<gProj, 256, GEMM_SMEM>>>(Dz, o, Dz, owt[l], Dz, y, Dz,
            ob[l], y, Dz, 0);
    }

    add_kernel<<<(M * Dz) / (256 * 4), 256>>>(x, y, x2);
    ln_kernel<<<M, 256>>>(x2, y, ln2_g, ln2_b);

    tgemm<<<gF1, 256, GEMM_SMEM>>>(Dz, y, Dz, w1t, Dz, hbuf, FFNz,
        b1, nullptr, 0, 1);
    tgemm<<<gProj, 256, GEMM_SMEM>>>(FFNz, hbuf, FFNz, w2t, FFNz, out, Dz,
        b2, x2, Dz, 0);
}

// round 6
// speedup vs baseline: 1.0017x; 1.0017x over previous
#include <cuda_runtime.h>
#include <cuda_bf16.h>
#include <cstdint>
#include <math.h>

// Problem constants
#define Bz   4
#define S1z  1024
#define S2z  1024
#define Dz   1024
#define Hz   16
#define DKz  64
#define FFNz 4096

// ---------------- scratch ----------------
__device__ float g_y  [Bz * S1z * Dz];
__device__ float g_kvn[Bz * S2z * Dz];
__device__ float g_q  [Bz * S1z * Dz];
__device__ float g_kv [(size_t)Bz * S2z * 4096];   // k0|v0|k1|v1 columns, ld=4096
__device__ float g_o  [Bz * S1z * Dz];
__device__ float g_x2 [Bz * S1z * Dz];
__device__ float g_h  [Bz * S1z * FFNz];
__device__ float g_wt [16 * 1024 * 1024];          // transposed weights

// ---------------- helpers ----------------
__device__ __forceinline__ uint32_t smem_u32(const void* p) {
    return (uint32_t)__cvta_generic_to_shared(p);
}
__device__ __forceinline__ void cp16(uint32_t dst, const void* src) {
    asm volatile("cp.async.cg.shared.global [%0], [%1], 16;" :: "r"(dst), "l"(src));
}
__device__ __forceinline__ void mma_tf32(float* c, const uint32_t* a, const uint32_t* b) {
    asm volatile("mma.sync.aligned.m16n8k8.row.col.f32.tf32.tf32.f32 "
                 "{%0,%1,%2,%3},{%4,%5,%6,%7},{%8,%9},{%0,%1,%2,%3};"
                 : "+f"(c[0]), "+f"(c[1]), "+f"(c[2]), "+f"(c[3])
                 : "r"(a[0]), "r"(a[1]), "r"(a[2]), "r"(a[3]), "r"(b[0]), "r"(b[1]));
}
__device__ __forceinline__ void ldsm4(uint32_t* r, uint32_t addr) {
    asm volatile("ldmatrix.sync.aligned.m8n8.x4.shared.b16 {%0,%1,%2,%3}, [%4];"
                 : "=r"(r[0]), "=r"(r[1]), "=r"(r[2]), "=r"(r[3]) : "r"(addr));
}

// ---------------- tf32 tensor-core GEMM (64x64 warp tiles) -------------------
// C[M,N] = A[M,K] @ Bt^T, A [M,K] and Bt [N,K] row-major (K contiguous).
// CTA 128x128, 4 warps (2x2 of 64x64), BK=16, 3-stage cp.async ring.
#define GSTR 20
#define GEMM_SMEM (3 * 2 * 128 * GSTR * 4)

__global__ void __launch_bounds__(128)
tgemm(int K,
      const float* __restrict__ A, int lda,
      const float* __restrict__ Bt, int ldb,
      float* __restrict__ C, int ldc,
      const float* __restrict__ bias,
      const float* __restrict__ res, int ldres, int relu)
{
    extern __shared__ __align__(16) float sm[];
    int tid = threadIdx.x;
    int bm = blockIdx.y * 128, bn = blockIdx.x * 128;
    int warp = tid >> 5, lane = tid & 31, g = lane >> 2, tg = lane & 3;
    int wn = warp & 1, wm = warp >> 1;          // 2x2 warp grid, 64x64 each

    uint32_t sb = smem_u32(sm);
    const int NT = K / 16;

    auto issue = [&](int t) {
        uint32_t base = sb + (uint32_t)((t % 3) * 256 * GSTR) * 4u;
        #pragma unroll
        for (int i = 0; i < 4; i++) {           // A: 128 rows x 16 floats
            int e = tid + i * 128, r = e >> 2, c = (e & 3) * 4;
            cp16(base + (uint32_t)(r * GSTR + c) * 4u,
                 A + (size_t)(bm + r) * lda + t * 16 + c);
        }
        #pragma unroll
        for (int i = 0; i < 4; i++) {           // B: 128 rows x 16 floats
            int e = tid + i * 128, r = e >> 2, c = (e & 3) * 4;
            cp16(base + (uint32_t)((128 + r) * GSTR + c) * 4u,
                 Bt + (size_t)(bn + r) * ldb + t * 16 + c);
        }
        asm volatile("cp.async.commit_group;");
    };

    int q = lane >> 3, rr = lane & 7;
    uint32_t a_off[4][2];
    #pragma unroll
    for (int mi = 0; mi < 4; mi++)
        #pragma unroll
        for (int ks = 0; ks < 2; ks++)
            a_off[mi][ks] = (uint32_t)(((wm*64 + mi*16 + (q&1)*8 + rr) * GSTR
                                        + ks*8 + (q>>1)*4) * 4);
    uint32_t b_off[4][2];
    #pragma unroll
    for (int jp = 0; jp < 4; jp++)
        #pragma unroll
        for (int ks = 0; ks < 2; ks++)
            b_off[jp][ks] = (uint32_t)(((128 + wn*64 + jp*16 + (q>>1)*8 + rr) * GSTR
                                        + ks*8 + (q&1)*4) * 4);

    float acc[4][8][4] = {};

    issue(0);
    if (NT > 1) issue(1);

    for (int t = 0; t < NT; t++) {
        if (t + 1 < NT) asm volatile("cp.async.wait_group 1;");
        else            asm volatile("cp.async.wait_group 0;");
        __syncthreads();
        if (t + 2 < NT) issue(t + 2);

        uint32_t stage = sb + (uint32_t)((t % 3) * 256 * GSTR) * 4u;
        #pragma unroll
        for (int ks = 0; ks < 2; ks++) {
            uint32_t a[4][4], b[4][4];
            #pragma unroll
            for (int mi = 0; mi < 4; mi++) ldsm4(a[mi], stage + a_off[mi][ks]);
            #pragma unroll
            for (int jp = 0; jp < 4; jp++) ldsm4(b[jp], stage + b_off[jp][ks]);
            #pragma unroll
            for (int mi = 0; mi < 4; mi++)
                #pragma unroll
                for (int jp = 0; jp < 4; jp++) {
                    mma_tf32(acc[mi][jp*2],     a[mi], &b[jp][0]);
                    mma_tf32(acc[mi][jp*2 + 1], a[mi], &b[jp][2]);
                }
        }
    }

    // epilogue
    #pragma unroll
    for (int mi = 0; mi < 4; mi++) {
        #pragma unroll
        for (int j = 0; j < 8; j++) {
            int m0 = bm + wm*64 + mi*16 + g;
            int n0 = bn + wn*64 + j*8 + 2*tg;
            float v0 = acc[mi][j][0], v1 = acc[mi][j][1];
            float v2 = acc[mi][j][2], v3 = acc[mi][j][3];
            if (bias) {
                float b0 = bias[n0], b1 = bias[n0 + 1];
                v0 += b0; v1 += b1; v2 += b0; v3 += b1;
            }
            if (res) {
                v0 += res[(size_t)m0*ldres + n0];
                v1 += res[(size_t)m0*ldres + n0 + 1];
                v2 += res[(size_t)(m0 + 8)*ldres + n0];
                v3 += res[(size_t)(m0 + 8)*ldres + n0 + 1];
            }
            if (relu) {
                v0 = fmaxf(v0, 0.f); v1 = fmaxf(v1, 0.f);
                v2 = fmaxf(v2, 0.f); v3 = fmaxf(v3, 0.f);
            }
            *(float2*)&C[(size_t)m0*ldc + n0]       = make_float2(v0, v1);
            *(float2*)&C[(size_t)(m0 + 8)*ldc + n0] = make_float2(v2, v3);
        }
    }
}

// ---------------- batched transpose for the 8 DxD weights --------------------
__global__ void transpose8_kernel(
    const float* s0, float* d0, const float* s1, float* d1,
    const float* s2, float* d2, const float* s3, float* d3,
    const float* s4, float* d4, const float* s5, float* d5,
    const float* s6, float* d6, const float* s7, float* d7)
{
    __shared__ float tile[32][33];
    const float* src; float* dst;
    switch (blockIdx.z) {
        case 0: src = s0; dst = d0; break;
        case 1: src = s1; dst = d1; break;
        case 2: src = s2; dst = d2; break;
        case 3: src = s3; dst = d3; break;
        case 4: src = s4; dst = d4; break;
        case 5: src = s5; dst = d5; break;
        case 6: src = s6; dst = d6; break;
        default: src = s7; dst = d7; break;
    }
    int tx = threadIdx.x, ty = threadIdx.y;
    int c0 = blockIdx.x * 32, r0 = blockIdx.y * 32;
    #pragma unroll
    for (int j = 0; j < 32; j += 8)
        tile[ty + j][tx] = src[(size_t)(r0 + ty + j) * Dz + c0 + tx];
    __syncthreads();
    #pragma unroll
    for (int j = 0; j < 32; j += 8)
        dst[(size_t)(c0 + ty + j) * Dz + r0 + tx] = tile[tx][ty + j];
}

__global__ void transpose_kernel(const float* __restrict__ src, float* __restrict__ dst,
                                 int R, int C)
{
    __shared__ float tile[32][33];
    int tx = threadIdx.x, ty = threadIdx.y;
    int c0 = blockIdx.x * 32, r0 = blockIdx.y * 32;
    #pragma unroll
    for (int j = 0; j < 32; j += 8)
        tile[ty + j][tx] = src[(size_t)(r0 + ty + j) * C + c0 + tx];
    __syncthreads();
    #pragma unroll
    for (int j = 0; j < 32; j += 8)
        dst[(size_t)(c0 + ty + j) * R + r0 + tx] = tile[tx][ty + j];
}

// ---------------- LayerNorm ----------------
__global__ void ln_kernel(const float* __restrict__ in, float* __restrict__ out,
                          const float* __restrict__ g, const float* __restrict__ bta)
{
    size_t row = blockIdx.x;
    int tid = threadIdx.x;
    const float4* xp = (const float4*)(in + row * (size_t)Dz);
    float4 v = xp[tid];
    float s = v.x + v.y + v.z + v.w;
    float q = v.x*v.x + v.y*v.y + v.z*v.z + v.w*v.w;
    #pragma unroll
    for (int o = 16; o; o >>= 1) {
        s += __shfl_xor_sync(0xffffffffu, s, o);
        q += __shfl_xor_sync(0xffffffffu, q, o);
    }
    __shared__ float ss[8], qq[8];
    int lane = tid & 31, wid = tid >> 5;
    if (!lane) { ss[wid] = s; qq[wid] = q; }
    __syncthreads();
    if (tid < 32) {
        s = (tid < 8) ? ss[tid] : 0.f;
        q = (tid < 8) ? qq[tid] : 0.f;
        #pragma unroll
        for (int o = 4; o; o >>= 1) {
            s += __shfl_xor_sync(0xffffffffu, s, o);
            q += __shfl_xor_sync(0xffffffffu, q, o);
        }
        if (!tid) { ss[0] = s; qq[0] = q; }
    }
    __syncthreads();
    float mean = ss[0] * (1.f / Dz);
    float var  = qq[0] * (1.f / Dz) - mean * mean;
    float inv  = rsqrtf(var + 1e-5f);
    float4 gv = ((const float4*)g)[tid];
    float4 bv = ((const float4*)bta)[tid];
    float4 o4;
    o4.x = (v.x - mean) * inv * gv.x + bv.x;
    o4.y = (v.y - mean) * inv * gv.y + bv.y;
    o4.z = (v.z - mean) * inv * gv.z + bv.z;
    o4.w = (v.w - mean) * inv * gv.w + bv.w;
    ((float4*)(out + row * (size_t)Dz))[tid] = o4;
}

// ---------------- elementwise add ----------------
__global__ void add_kernel(const float* __restrict__ a, const float* __restrict__ b,
                           float* __restrict__ c)
{
    int i = blockIdx.x * blockDim.x + threadIdx.x;
    float4 av = ((const float4*)a)[i];
    float4 bv = ((const float4*)b)[i];
    float4 cv;
    cv.x = av.x + bv.x; cv.y = av.y + bv.y; cv.z = av.z + bv.z; cv.w = av.w + bv.w;
    ((float4*)c)[i] = cv;
}

// ---------------- fused flash cross-attention --------------------------------
#define KSTR 68
#define VSTR 72
#define PSTR 68
#define FLASH_SMEM ((2*64*KSTR + 2*64*VSTR + 128*PSTR + S2z) * 4)

__global__ void __launch_bounds__(256)
flash_kernel(const float* __restrict__ Q, const float* __restrict__ Kg,
             const float* __restrict__ Vg, int ldkv,
             const int* __restrict__ mask, float* __restrict__ O)
{
    extern __shared__ float sm[];
    float* Ks = sm;
    float* Vs = Ks + 2*64*KSTR;
    float* Ps = Vs + 2*64*VSTR;
    float* Mf = Ps + 128*PSTR;

    int bh = blockIdx.y;
    int b = bh / Hz, h = bh % Hz;
    int q0 = blockIdx.x * 128;
    int tid = threadIdx.x, warp = tid >> 5, lane = tid & 31, g = lane >> 2, tg = lane & 3;

    const float* Qb = Q  + ((size_t)(b*S1z + q0))*Dz + h*DKz;
    const float* Kb = Kg + (size_t)b*S2z*ldkv + h*DKz;
    const float* Vb = Vg + (size_t)b*S2z*ldkv + h*DKz;

    for (int i = tid; i < S2z; i += 256) Mf[i] = mask[(size_t)b*S2z + i] ? 1.f : 0.f;

    uint32_t qa[8][4];
    {
        int ml = warp*16 + g, mh = ml + 8;
        #pragma unroll
        for (int ki = 0; ki < 8; ki++) {
            qa[ki][0] = __float_as_uint(Qb[(size_t)ml*Dz + ki*8 + tg]);
            qa[ki][1] = __float_as_uint(Qb[(size_t)mh*Dz + ki*8 + tg]);
            qa[ki][2] = __float_as_uint(Qb[(size_t)ml*Dz + ki*8 + tg + 4]);
            qa[ki][3] = __float_as_uint(Qb[(size_t)mh*Dz + ki*8 + tg + 4]);
        }
    }

    uint32_t ksb = smem_u32(Ks);
    uint32_t vsb = smem_u32(Vs);

    auto issue = [&](int t) {
        int buf = t & 1;
        #pragma unroll
        for (int i = 0; i < 4; i++) {
            int e = tid + i*256;
            int r = e >> 4, c = (e & 15) * 4;
            cp16(ksb + (uint32_t)(buf*64*KSTR + r*KSTR + c)*4u,
                 Kb + (size_t)(t*64 + r)*ldkv + c);
            cp16(vsb + (uint32_t)(buf*64*VSTR + r*VSTR + c)*4u,
                 Vb + (size_t)(t*64 + r)*ldkv + c);
        }
        asm volatile("cp.async.commit_group;");
    };

    float s_acc[8][4];
    float o_acc[8][4] = {};
    float m_lo = -INFINITY, m_hi = -INFINITY, l_lo = 0.f, l_hi = 0.f;
    int rl = warp*16 + g, rh = rl + 8;

    issue(0);
    for (int t = 0; t < S2z/64; t++) {
        if (t + 1 < S2z/64) { issue(t + 1); asm volatile("cp.async.wait_group 1;"); }
        else                { asm volatile("cp.async.wait_group 0;"); }
        __syncthreads();
        int buf = t & 1;
        const float* kp = Ks + buf*64*KSTR;
        const float* vp = Vs + buf*64*VSTR;

        #pragma unroll
        for (int j = 0; j < 8; j++)
            s_acc[j][0] = s_acc[j][1] = s_acc[j][2] = s_acc[j][3] = 0.f;
        #pragma unroll
        for (int ki = 0; ki < 8; ki++) {
            #pragma unroll
            for (int j = 0; j < 8; j++) {
                int n0 = j*8 + g;
                uint32_t bb[2] = {
                    __float_as_uint(kp[n0*KSTR + ki*8 + tg]),
                    __float_as_uint(kp[n0*KSTR + ki*8 + tg + 4]) };
                mma_tf32(s_acc[j], qa[ki], bb);
            }
        }

        float rmax_lo = -INFINITY, rmax_hi = -INFINITY;
        #pragma unroll
        for (int j = 0; j < 8; j++) {
            int c0 = t*64 + j*8 + 2*tg;
            float mf0 = Mf[c0], mf1 = Mf[c0 + 1];
            s_acc[j][0] = (mf0 != 0.f) ? s_acc[j][0]*0.125f : -1e9f;
            s_acc[j][1] = (mf1 != 0.f) ? s_acc[j][1]*0.125f : -1e9f;
            s_acc[j][2] = (mf0 != 0.f) ? s_acc[j][2]*0.125f : -1e9f;
            s_acc[j][3] = (mf1 != 0.f) ? s_acc[j][3]*0.125f : -1e9f;
            rmax_lo = fmaxf(rmax_lo, fmaxf(s_acc[j][0], s_acc[j][1]));
            rmax_hi = fmaxf(rmax_hi, fmaxf(s_acc[j][2], s_acc[j][3]));
        }
        rmax_lo = fmaxf(rmax_lo, __shfl_xor_sync(0xffffffffu, rmax_lo, 1));
        rmax_lo = fmaxf(rmax_lo, __shfl_xor_sync(0xffffffffu, rmax_lo, 2));
        rmax_hi = fmaxf(rmax_hi, __shfl_xor_sync(0xffffffffu, rmax_hi, 1));
        rmax_hi = fmaxf(rmax_hi, __shfl_xor_sync(0xffffffffu, rmax_hi, 2));
        float mn_lo = fmaxf(m_lo, rmax_lo), mn_hi = fmaxf(m_hi, rmax_hi);
        float al_lo = __expf(m_lo - mn_lo), al_hi = __expf(m_hi - mn_hi);
        m_lo = mn_lo; m_hi = mn_hi;

        float sum_lo = 0.f, sum_hi = 0.f;
        #pragma unroll
        for (int j = 0; j < 8; j++) {
            float p0 = __expf(s_acc[j][0] - mn_lo);
            float p1 = __expf(s_acc[j][1] - mn_lo);
            float p2 = __expf(s_acc[j][2] - mn_hi);
            float p3 = __expf(s_acc[j][3] - mn_hi);
            sum_lo += p0 + p1; sum_hi += p2 + p3;
            int c = j*8 + 2*tg;
            *(float2*)&Ps[rl*PSTR + c] = make_float2(p0, p1);
            *(float2*)&Ps[rh*PSTR + c] = make_float2(p2, p3);
        }
        sum_lo += __shfl_xor_sync(0xffffffffu, sum_lo, 1);
        sum_lo += __shfl_xor_sync(0xffffffffu, sum_lo, 2);
        sum_hi += __shfl_xor_sync(0xffffffffu, sum_hi, 1);
        sum_hi += __shfl_xor_sync(0xffffffffu, sum_hi, 2);
        l_lo = al_lo*l_lo + sum_lo;
        l_hi = al_hi*l_hi + sum_hi;
        #pragma unroll
        for (int j = 0; j < 8; j++) {
            o_acc[j][0] *= al_lo; o_acc[j][1] *= al_lo;
            o_acc[j][2] *= al_hi; o_acc[j][3] *= al_hi;
        }
        __syncwarp();

        #pragma unroll
        for (int ki = 0; ki < 8; ki++) {
            int k0 = ki*8 + tg;
            uint32_t pa[4];
            pa[0] = __float_as_uint(Ps[rl*PSTR + k0]);
            pa[1] = __float_as_uint(Ps[rh*PSTR + k0]);
            pa[2] = __float_as_uint(Ps[rl*PSTR + k0 + 4]);
            pa[3] = __float_as_uint(Ps[rh*PSTR + k0 + 4]);
            #pragma unroll
            for (int j = 0; j < 8; j++) {
                int n0 = j*8 + g;
                uint32_t bb[2] = {
                    __float_as_uint(vp[(ki*8 + tg    )*VSTR + n0]),
                    __float_as_uint(vp[(ki*8 + tg + 4)*VSTR + n0]) };
                mma_tf32(o_acc[j], pa, bb);
            }
        }
        __syncthreads();
    }

    float il_lo = 1.f / l_lo, il_hi = 1.f / l_hi;
    float* Ob = O + ((size_t)(b*S1z + q0))*Dz + h*DKz;
    #pragma unroll
    for (int j = 0; j < 8; j++) {
        int c = j*8 + 2*tg;
        *(float2*)&Ob[(size_t)rl*Dz + c] =
            make_float2(o_acc[j][0]*il_lo, o_acc[j][1]*il_lo);
        *(float2*)&Ob[(size_t)rh*Dz + c] =
            make_float2(o_acc[j][2]*il_hi, o_acc[j][3]*il_hi);
    }
}

// ---------------- host orchestration ----------------
extern "C" void kernel_launch(void* const* d_in, const int* in_sizes, int n_in,
                              void* d_out, int out_size)
{
    const float* x     = (const float*)d_in[0];
    const float* kv    = (const float*)d_in[1];
    const int*   mask  = (const int*)  d_in[2];
    const float* ln1_g = (const float*)d_in[3];
    const float* ln1_b = (const float*)d_in[4];
    const float* qw[2] = { (const float*)d_in[5],  (const float*)d_in[10] };
    const float* kw[2] = { (const float*)d_in[6],  (const float*)d_in[11] };
    const float* vw[2] = { (const float*)d_in[7],  (const float*)d_in[12] };
    const float* ow[2] = { (const float*)d_in[8],  (const float*)d_in[13] };
    const float* ob[2] = { (const float*)d_in[9],  (const float*)d_in[14] };
    const float* ln2_g = (const float*)d_in[15];
    const float* ln2_b = (const float*)d_in[16];
    const float* w1    = (const float*)d_in[17];
    const float* b1    = (const float*)d_in[18];
    const float* w2    = (const float*)d_in[19];
    const float* b2    = (const float*)d_in[20];
    float* out = (float*)d_out;

    float *y, *kvn, *q, *kvbuf, *o, *x2, *hbuf, *wt;
    cudaGetSymbolAddress((void**)&y,     g_y);
    cudaGetSymbolAddress((void**)&kvn,   g_kvn);
    cudaGetSymbolAddress((void**)&q,     g_q);
    cudaGetSymbolAddress((void**)&kvbuf, g_kv);
    cudaGetSymbolAddress((void**)&o,     g_o);
    cudaGetSymbolAddress((void**)&x2,    g_x2);
    cudaGetSymbolAddress((void**)&hbuf,  g_h);
    cudaGetSymbolAddress((void**)&wt,    g_wt);

    cudaFuncSetAttribute(flash_kernel,
        cudaFuncAttributeMaxDynamicSharedMemorySize, FLASH_SMEM);
    cudaFuncSetAttribute(tgemm,
        cudaFuncAttributeMaxDynamicSharedMemorySize, GEMM_SMEM);

    const int M = Bz * S1z;   // 4096
    const size_t MM = 1024 * 1024;

    float* qwt[2] = { wt + 0*MM, wt + 1*MM };
    float* owt[2] = { wt + 2*MM, wt + 3*MM };
    float* kvwt   = wt + 4*MM;   // rows: kw0^T | vw0^T | kw1^T | vw1^T  [4096,1024]
    float* w1t    = wt + 8*MM;   // [4096,1024]
    float* w2t    = wt + 12*MM;  // [1024,4096]

    // one batched transpose for the 8 DxD weights, KV weights land concatenated
    dim3 tb(32, 8);
    transpose8_kernel<<<dim3(32,32,8), tb>>>(
        qw[0], qwt[0], qw[1], qwt[1], ow[0], owt[0], ow[1], owt[1],
        kw[0], kvwt + 0*MM, vw[0], kvwt + 1*MM, kw[1], kvwt + 2*MM, vw[1], kvwt + 3*MM);
    transpose_kernel<<<dim3(FFNz/32, Dz/32), tb>>>(w1, w1t, Dz, FFNz);
    transpose_kernel<<<dim3(Dz/32, FFNz/32), tb>>>(w2, w2t, FFNz, Dz);

    ln_kernel<<<Bz * S1z, 256>>>(x,  y,   ln1_g, ln1_b);
    ln_kernel<<<Bz * S2z, 256>>>(kv, kvn, ln1_g, ln1_b);

    dim3 gProj(Dz/128, M/128);      // (8, 32)
    dim3 gKV(4096/128, M/128);      // (32, 32)
    dim3 gFlash(S1z/128, Bz*Hz);    // (8, 64)
    dim3 gF1(FFNz/128, M/128);      // (32, 32)

    // all four K/V projections in one GEMM (kvn is layer-invariant)
    tgemm<<<gKV, 128, GEMM_SMEM>>>(Dz, kvn, Dz, kvwt, Dz, kvbuf, 4096,
        nullptr, nullptr, 0, 0);

    for (int l = 0; l < 2; l++) {
        tgemm<<<gProj, 128, GEMM_SMEM>>>(Dz, y, Dz, qwt[l], Dz, q, Dz,
            nullptr, nullptr, 0, 0);

        flash_kernel<<<gFlash, 256, FLASH_SMEM>>>(
            q, kvbuf + l*2048, kvbuf + l*2048 + 1024, 4096, mask, o);

        tgemm<<<gProj, 128, GEMM_SMEM>>>(Dz, o, Dz, owt[l], Dz, y, Dz,
            ob[l], y, Dz, 0);
    }

    add_kernel<<<(M * Dz) / (256 * 4), 256>>>(x, y, x2);
    ln_kernel<<<M, 256>>>(x2, y, ln2_g, ln2_b);

    tgemm<<<gF1, 128, GEMM_SMEM>>>(Dz, y, Dz, w1t, Dz, hbuf, FFNz,
        b1, nullptr, 0, 1);
    tgemm<<<gProj, 128, GEMM_SMEM>>>(FFNz, hbuf, FFNz, w2t, FFNz, out, Dz,
        b2, x2, Dz, 0);
}

// round 7
// speedup vs baseline: 1.5515x; 1.5489x over previous
#include <cuda_runtime.h>
#include <cuda_fp16.h>
#include <cstdint>
#include <math.h>

// Problem constants
#define Bz   4
#define S1z  1024
#define S2z  1024
#define Dz   1024
#define Hz   16
#define DKz  64
#define FFNz 4096

// ---------------- scratch ----------------
__device__ float  g_y   [Bz * S1z * Dz];
__device__ float  g_q   [Bz * S1z * Dz];
__device__ float  g_kv  [(size_t)Bz * S2z * 4096];  // k0|v0|k1|v1, ld=4096 (fp32, flash input)
__device__ float  g_x2  [Bz * S1z * Dz];
__device__ __half g_y16  [Bz * S1z * Dz];
__device__ __half g_kvn16[Bz * S2z * Dz];
__device__ __half g_o16  [Bz * S1z * Dz];
__device__ __half g_yf16 [Bz * S1z * Dz];
__device__ __half g_h16  [(size_t)Bz * S1z * FFNz];
__device__ __half g_wth  [16 * 1024 * 1024];        // fp16 transposed weights

// ---------------- helpers ----------------
__device__ __forceinline__ uint32_t smem_u32(const void* p) {
    return (uint32_t)__cvta_generic_to_shared(p);
}
__device__ __forceinline__ void cp16(uint32_t dst, const void* src) {
    asm volatile("cp.async.cg.shared.global [%0], [%1], 16;" :: "r"(dst), "l"(src));
}
__device__ __forceinline__ void mma_f16(float* c, const uint32_t* a, const uint32_t* b) {
    asm volatile("mma.sync.aligned.m16n8k16.row.col.f32.f16.f16.f32 "
                 "{%0,%1,%2,%3},{%4,%5,%6,%7},{%8,%9},{%0,%1,%2,%3};"
                 : "+f"(c[0]), "+f"(c[1]), "+f"(c[2]), "+f"(c[3])
                 : "r"(a[0]), "r"(a[1]), "r"(a[2]), "r"(a[3]), "r"(b[0]), "r"(b[1]));
}
__device__ __forceinline__ void mma_tf32(float* c, const uint32_t* a, const uint32_t* b) {
    asm volatile("mma.sync.aligned.m16n8k8.row.col.f32.tf32.tf32.f32 "
                 "{%0,%1,%2,%3},{%4,%5,%6,%7},{%8,%9},{%0,%1,%2,%3};"
                 : "+f"(c[0]), "+f"(c[1]), "+f"(c[2]), "+f"(c[3])
                 : "r"(a[0]), "r"(a[1]), "r"(a[2]), "r"(a[3]), "r"(b[0]), "r"(b[1]));
}
__device__ __forceinline__ void ldsm4(uint32_t* r, uint32_t addr) {
    asm volatile("ldmatrix.sync.aligned.m8n8.x4.shared.b16 {%0,%1,%2,%3}, [%4];"
                 : "=r"(r[0]), "=r"(r[1]), "=r"(r[2]), "=r"(r[3]) : "r"(addr));
}

// ---------------- fp16 tensor-core GEMM --------------------------------------
// C = A[M,K] @ Bt^T ; A [M,K] fp16, Bt [N,K] fp16 (K contiguous).
// CTA 128x128, 8 warps (4x2 of 32x64), BK=32, 3-stage cp.async ring.
// Outputs: C32 (fp32, optional) and/or C16 (fp16, optional), bias/res fp32.
#define HSTR 40                                   // halves per SMEM row (32+8)
#define HSTAGE (256 * HSTR * 2)                   // bytes per stage (A rows 0-127, B rows 128-255)
#define GEMM_SMEM (3 * HSTAGE)

__global__ void __launch_bounds__(256)
hgemm(int K,
      const __half* __restrict__ A, int lda,
      const __half* __restrict__ Bt, int ldb,
      float* __restrict__ C32, __half* __restrict__ C16, int ldc,
      const float* __restrict__ bias,
      const float* __restrict__ res, int ldres, int relu)
{
    extern __shared__ __align__(16) char smc[];
    int tid = threadIdx.x;
    int bm = blockIdx.y * 128, bn = blockIdx.x * 128;
    int warp = tid >> 5, lane = tid & 31, g = lane >> 2, tg = lane & 3;
    int wn = warp & 1, wm = warp >> 1;            // 4x2 grid: WM=32, WN=64

    uint32_t sb = smem_u32(smc);
    const int NT = K / 32;

    auto issue = [&](int t) {
        uint32_t base = sb + (uint32_t)((t % 3) * HSTAGE);
        #pragma unroll
        for (int i = 0; i < 2; i++) {             // A: 128 rows x 32 halves (64B)
            int e = tid + i * 256, r = e >> 2, c = (e & 3) * 8;
            cp16(base + (uint32_t)(r * HSTR + c) * 2u,
                 A + (size_t)(bm + r) * lda + t * 32 + c);
        }
        #pragma unroll
        for (int i = 0; i < 2; i++) {             // B: 128 rows
            int e = tid + i * 256, r = e >> 2, c = (e & 3) * 8;
            cp16(base + (uint32_t)((128 + r) * HSTR + c) * 2u,
                 Bt + (size_t)(bn + r) * ldb + t * 32 + c);
        }
        asm volatile("cp.async.commit_group;");
    };

    int q = lane >> 3, rr = lane & 7;
    // A frag (mi, ks): ldsm x4, sub-matrix q: rows +(q&1)*8, khalf +(q>>1)*8
    uint32_t a_off[2][2];
    #pragma unroll
    for (int mi = 0; mi < 2; mi++)
        #pragma unroll
        for (int ks = 0; ks < 2; ks++)
            a_off[mi][ks] = (uint32_t)(((wm*32 + mi*16 + (q&1)*8 + rr) * HSTR
                                        + ks*16 + (q>>1)*8) * 2);
    // B frag (jp covers n-octets 2jp,2jp+1; ks): sub q: n +(q>>1)*8, khalf +(q&1)*8
    uint32_t b_off[4][2];
    #pragma unroll
    for (int jp = 0; jp < 4; jp++)
        #pragma unroll
        for (int ks = 0; ks < 2; ks++)
            b_off[jp][ks] = (uint32_t)(((128 + wn*64 + jp*16 + (q>>1)*8 + rr) * HSTR
                                        + ks*16 + (q&1)*8) * 2);

    float acc[2][8][4] = {};

    issue(0);
    if (NT > 1) issue(1);

    for (int t = 0; t < NT; t++) {
        if (t + 1 < NT) asm volatile("cp.async.wait_group 1;");
        else            asm volatile("cp.async.wait_group 0;");
        __syncthreads();
        if (t + 2 < NT) issue(t + 2);

        uint32_t stage = sb + (uint32_t)((t % 3) * HSTAGE);
        #pragma unroll
        for (int ks = 0; ks < 2; ks++) {
            uint32_t a[2][4], b[4][4];
            #pragma unroll
            for (int mi = 0; mi < 2; mi++) ldsm4(a[mi], stage + a_off[mi][ks]);
            #pragma unroll
            for (int jp = 0; jp < 4; jp++) ldsm4(b[jp], stage + b_off[jp][ks]);
            #pragma unroll
            for (int mi = 0; mi < 2; mi++)
                #pragma unroll
                for (int jp = 0; jp < 4; jp++) {
                    mma_f16(acc[mi][jp*2],     a[mi], &b[jp][0]);
                    mma_f16(acc[mi][jp*2 + 1], a[mi], &b[jp][2]);
                }
        }
    }

    // epilogue
    #pragma unroll
    for (int mi = 0; mi < 2; mi++) {
        #pragma unroll
        for (int j = 0; j < 8; j++) {
            int m0 = bm + wm*32 + mi*16 + g;
            int n0 = bn + wn*64 + j*8 + 2*tg;
            float v0 = acc[mi][j][0], v1 = acc[mi][j][1];
            float v2 = acc[mi][j][2], v3 = acc[mi][j][3];
            if (bias) {
                float b0 = bias[n0], b1 = bias[n0 + 1];
                v0 += b0; v1 += b1; v2 += b0; v3 += b1;
            }
            if (res) {
                v0 += res[(size_t)m0*ldres + n0];
                v1 += res[(size_t)m0*ldres + n0 + 1];
                v2 += res[(size_t)(m0 + 8)*ldres + n0];
                v3 += res[(size_t)(m0 + 8)*ldres + n0 + 1];
            }
            if (relu) {
                v0 = fmaxf(v0, 0.f); v1 = fmaxf(v1, 0.f);
                v2 = fmaxf(v2, 0.f); v3 = fmaxf(v3, 0.f);
            }
            if (C32) {
                *(float2*)&C32[(size_t)m0*ldc + n0]       = make_float2(v0, v1);
                *(float2*)&C32[(size_t)(m0 + 8)*ldc + n0] = make_float2(v2, v3);
            }
            if (C16) {
                *(__half2*)&C16[(size_t)m0*ldc + n0]       = __floats2half2_rn(v0, v1);
                *(__half2*)&C16[(size_t)(m0 + 8)*ldc + n0] = __floats2half2_rn(v2, v3);
            }
        }
    }
}

// ---------------- transpose + fp32->fp16 convert -----------------------------
__global__ void transpose8_kernel(
    const float* s0, __half* d0, const float* s1, __half* d1,
    const float* s2, __half* d2, const float* s3, __half* d3,
    const float* s4, __half* d4, const float* s5, __half* d5,
    const float* s6, __half* d6, const float* s7, __half* d7)
{
    __shared__ float tile[32][33];
    const float* src; __half* dst;
    switch (blockIdx.z) {
        case 0: src = s0; dst = d0; break;
        case 1: src = s1; dst = d1; break;
        case 2: src = s2; dst = d2; break;
        case 3: src = s3; dst = d3; break;
        case 4: src = s4; dst = d4; break;
        case 5: src = s5; dst = d5; break;
        case 6: src = s6; dst = d6; break;
        default: src = s7; dst = d7; break;
    }
    int tx = threadIdx.x, ty = threadIdx.y;
    int c0 = blockIdx.x * 32, r0 = blockIdx.y * 32;
    #pragma unroll
    for (int j = 0; j < 32; j += 8)
        tile[ty + j][tx] = src[(size_t)(r0 + ty + j) * Dz + c0 + tx];
    __syncthreads();
    #pragma unroll
    for (int j = 0; j < 32; j += 8)
        dst[(size_t)(c0 + ty + j) * Dz + r0 + tx] = __float2half_rn(tile[tx][ty + j]);
}

__global__ void transpose_kernel(const float* __restrict__ src, __half* __restrict__ dst,
                                 int R, int C)
{
    __shared__ float tile[32][33];
    int tx = threadIdx.x, ty = threadIdx.y;
    int c0 = blockIdx.x * 32, r0 = blockIdx.y * 32;
    #pragma unroll
    for (int j = 0; j < 32; j += 8)
        tile[ty + j][tx] = src[(size_t)(r0 + ty + j) * C + c0 + tx];
    __syncthreads();
    #pragma unroll
    for (int j = 0; j < 32; j += 8)
        dst[(size_t)(c0 + ty + j) * R + r0 + tx] = __float2half_rn(tile[tx][ty + j]);
}

// ---------------- LayerNorm (dual fp32/fp16 outputs, both optional) ----------
__global__ void ln_kernel(const float* __restrict__ in, float* __restrict__ out32,
                          __half* __restrict__ out16,
                          const float* __restrict__ g, const float* __restrict__ bta)
{
    size_t row = blockIdx.x;
    int tid = threadIdx.x;
    const float4* xp = (const float4*)(in + row * (size_t)Dz);
    float4 v = xp[tid];
    float s = v.x + v.y + v.z + v.w;
    float q = v.x*v.x + v.y*v.y + v.z*v.z + v.w*v.w;
    #pragma unroll
    for (int o = 16; o; o >>= 1) {
        s += __shfl_xor_sync(0xffffffffu, s, o);
        q += __shfl_xor_sync(0xffffffffu, q, o);
    }
    __shared__ float ss[8], qq[8];
    int lane = tid & 31, wid = tid >> 5;
    if (!lane) { ss[wid] = s; qq[wid] = q; }
    __syncthreads();
    if (tid < 32) {
        s = (tid < 8) ? ss[tid] : 0.f;
        q = (tid < 8) ? qq[tid] : 0.f;
        #pragma unroll
        for (int o = 4; o; o >>= 1) {
            s += __shfl_xor_sync(0xffffffffu, s, o);
            q += __shfl_xor_sync(0xffffffffu, q, o);
        }
        if (!tid) { ss[0] = s; qq[0] = q; }
    }
    __syncthreads();
    float mean = ss[0] * (1.f / Dz);
    float var  = qq[0] * (1.f / Dz) - mean * mean;
    float inv  = rsqrtf(var + 1e-5f);
    float4 gv = ((const float4*)g)[tid];
    float4 bv = ((const float4*)bta)[tid];
    float4 o4;
    o4.x = (v.x - mean) * inv * gv.x + bv.x;
    o4.y = (v.y - mean) * inv * gv.y + bv.y;
    o4.z = (v.z - mean) * inv * gv.z + bv.z;
    o4.w = (v.w - mean) * inv * gv.w + bv.w;
    if (out32) ((float4*)(out32 + row * (size_t)Dz))[tid] = o4;
    if (out16) {
        __half2 h0 = __floats2half2_rn(o4.x, o4.y);
        __half2 h1 = __floats2half2_rn(o4.z, o4.w);
        uint2 u = make_uint2(*(uint32_t*)&h0, *(uint32_t*)&h1);
        ((uint2*)(out16 + row * (size_t)Dz))[tid] = u;
    }
}

// ---------------- elementwise add ----------------
__global__ void add_kernel(const float* __restrict__ a, const float* __restrict__ b,
                           float* __restrict__ c)
{
    int i = blockIdx.x * blockDim.x + threadIdx.x;
    float4 av = ((const float4*)a)[i];
    float4 bv = ((const float4*)b)[i];
    float4 cv;
    cv.x = av.x + bv.x; cv.y = av.y + bv.y; cv.z = av.z + bv.z; cv.w = av.w + bv.w;
    ((float4*)c)[i] = cv;
}

// ---------------- fused flash cross-attention (tf32, fp16 output) ------------
#define KSTR 68
#define VSTR 72
#define PSTR 68
#define FLASH_SMEM ((2*64*KSTR + 2*64*VSTR + 128*PSTR + S2z) * 4)

__global__ void __launch_bounds__(256)
flash_kernel(const float* __restrict__ Q, const float* __restrict__ Kg,
             const float* __restrict__ Vg, int ldkv,
             const int* __restrict__ mask, __half* __restrict__ O16)
{
    extern __shared__ float sm[];
    float* Ks = sm;
    float* Vs = Ks + 2*64*KSTR;
    float* Ps = Vs + 2*64*VSTR;
    float* Mf = Ps + 128*PSTR;

    int bh = blockIdx.y;
    int b = bh / Hz, h = bh % Hz;
    int q0 = blockIdx.x * 128;
    int tid = threadIdx.x, warp = tid >> 5, lane = tid & 31, g = lane >> 2, tg = lane & 3;

    const float* Qb = Q  + ((size_t)(b*S1z + q0))*Dz + h*DKz;
    const float* Kb = Kg + (size_t)b*S2z*ldkv + h*DKz;
    const float* Vb = Vg + (size_t)b*S2z*ldkv + h*DKz;

    for (int i = tid; i < S2z; i += 256) Mf[i] = mask[(size_t)b*S2z + i] ? 1.f : 0.f;

    uint32_t qa[8][4];
    {
        int ml = warp*16 + g, mh = ml + 8;
        #pragma unroll
        for (int ki = 0; ki < 8; ki++) {
            qa[ki][0] = __float_as_uint(Qb[(size_t)ml*Dz + ki*8 + tg]);
            qa[ki][1] = __float_as_uint(Qb[(size_t)mh*Dz + ki*8 + tg]);
            qa[ki][2] = __float_as_uint(Qb[(size_t)ml*Dz + ki*8 + tg + 4]);
            qa[ki][3] = __float_as_uint(Qb[(size_t)mh*Dz + ki*8 + tg + 4]);
        }
    }

    uint32_t ksb = smem_u32(Ks);
    uint32_t vsb = smem_u32(Vs);

    auto issue = [&](int t) {
        int buf = t & 1;
        #pragma unroll
        for (int i = 0; i < 4; i++) {
            int e = tid + i*256;
            int r = e >> 4, c = (e & 15) * 4;
            cp16(ksb + (uint32_t)(buf*64*KSTR + r*KSTR + c)*4u,
                 Kb + (size_t)(t*64 + r)*ldkv + c);
            cp16(vsb + (uint32_t)(buf*64*VSTR + r*VSTR + c)*4u,
                 Vb + (size_t)(t*64 + r)*ldkv + c);
        }
        asm volatile("cp.async.commit_group;");
    };

    float s_acc[8][4];
    float o_acc[8][4] = {};
    float m_lo = -INFINITY, m_hi = -INFINITY, l_lo = 0.f, l_hi = 0.f;
    int rl = warp*16 + g, rh = rl + 8;

    issue(0);
    for (int t = 0; t < S2z/64; t++) {
        if (t + 1 < S2z/64) { issue(t + 1); asm volatile("cp.async.wait_group 1;"); }
        else                { asm volatile("cp.async.wait_group 0;"); }
        __syncthreads();
        int buf = t & 1;
        const float* kp = Ks + buf*64*KSTR;
        const float* vp = Vs + buf*64*VSTR;

        #pragma unroll
        for (int j = 0; j < 8; j++)
            s_acc[j][0] = s_acc[j][1] = s_acc[j][2] = s_acc[j][3] = 0.f;
        #pragma unroll
        for (int ki = 0; ki < 8; ki++) {
            #pragma unroll
            for (int j = 0; j < 8; j++) {
                int n0 = j*8 + g;
                uint32_t bb[2] = {
                    __float_as_uint(kp[n0*KSTR + ki*8 + tg]),
                    __float_as_uint(kp[n0*KSTR + ki*8 + tg + 4]) };
                mma_tf32(s_acc[j], qa[ki], bb);
            }
        }

        float rmax_lo = -INFINITY, rmax_hi = -INFINITY;
        #pragma unroll
        for (int j = 0; j < 8; j++) {
            int c0 = t*64 + j*8 + 2*tg;
            float mf0 = Mf[c0], mf1 = Mf[c0 + 1];
            s_acc[j][0] = (mf0 != 0.f) ? s_acc[j][0]*0.125f : -1e9f;
            s_acc[j][1] = (mf1 != 0.f) ? s_acc[j][1]*0.125f : -1e9f;
            s_acc[j][2] = (mf0 != 0.f) ? s_acc[j][2]*0.125f : -1e9f;
            s_acc[j][3] = (mf1 != 0.f) ? s_acc[j][3]*0.125f : -1e9f;
            rmax_lo = fmaxf(rmax_lo, fmaxf(s_acc[j][0], s_acc[j][1]));
            rmax_hi = fmaxf(rmax_hi, fmaxf(s_acc[j][2], s_acc[j][3]));
        }
        rmax_lo = fmaxf(rmax_lo, __shfl_xor_sync(0xffffffffu, rmax_lo, 1));
        rmax_lo = fmaxf(rmax_lo, __shfl_xor_sync(0xffffffffu, rmax_lo, 2));
        rmax_hi = fmaxf(rmax_hi, __shfl_xor_sync(0xffffffffu, rmax_hi, 1));
        rmax_hi = fmaxf(rmax_hi, __shfl_xor_sync(0xffffffffu, rmax_hi, 2));
        float mn_lo = fmaxf(m_lo, rmax_lo), mn_hi = fmaxf(m_hi, rmax_hi);
        float al_lo = __expf(m_lo - mn_lo), al_hi = __expf(m_hi - mn_hi);
        m_lo = mn_lo; m_hi = mn_hi;

        float sum_lo = 0.f, sum_hi = 0.f;
        #pragma unroll
        for (int j = 0; j < 8; j++) {
            float p0 = __expf(s_acc[j][0] - mn_lo);
            float p1 = __expf(s_acc[j][1] - mn_lo);
            float p2 = __expf(s_acc[j][2] - mn_hi);
            float p3 = __expf(s_acc[j][3] - mn_hi);
            sum_lo += p0 + p1; sum_hi += p2 + p3;
            int c = j*8 + 2*tg;
            *(float2*)&Ps[rl*PSTR + c] = make_float2(p0, p1);
            *(float2*)&Ps[rh*PSTR + c] = make_float2(p2, p3);
        }
        sum_lo += __shfl_xor_sync(0xffffffffu, sum_lo, 1);
        sum_lo += __shfl_xor_sync(0xffffffffu, sum_lo, 2);
        sum_hi += __shfl_xor_sync(0xffffffffu, sum_hi, 1);
        sum_hi += __shfl_xor_sync(0xffffffffu, sum_hi, 2);
        l_lo = al_lo*l_lo + sum_lo;
        l_hi = al_hi*l_hi + sum_hi;
        #pragma unroll
        for (int j = 0; j < 8; j++) {
            o_acc[j][0] *= al_lo; o_acc[j][1] *= al_lo;
            o_acc[j][2] *= al_hi; o_acc[j][3] *= al_hi;
        }
        __syncwarp();

        #pragma unroll
        for (int ki = 0; ki < 8; ki++) {
            int k0 = ki*8 + tg;
            uint32_t pa[4];
            pa[0] = __float_as_uint(Ps[rl*PSTR + k0]);
            pa[1] = __float_as_uint(Ps[rh*PSTR + k0]);
            pa[2] = __float_as_uint(Ps[rl*PSTR + k0 + 4]);
            pa[3] = __float_as_uint(Ps[rh*PSTR + k0 + 4]);
            #pragma unroll
            for (int j = 0; j < 8; j++) {
                int n0 = j*8 + g;
                uint32_t bb[2] = {
                    __float_as_uint(vp[(ki*8 + tg    )*VSTR + n0]),
                    __float_as_uint(vp[(ki*8 + tg + 4)*VSTR + n0]) };
                mma_tf32(o_acc[j], pa, bb);
            }
        }
        __syncthreads();
    }

    float il_lo = 1.f / l_lo, il_hi = 1.f / l_hi;
    __half* Ob = O16 + ((size_t)(b*S1z + q0))*Dz + h*DKz;
    #pragma unroll
    for (int j = 0; j < 8; j++) {
        int c = j*8 + 2*tg;
        *(__half2*)&Ob[(size_t)rl*Dz + c] =
            __floats2half2_rn(o_acc[j][0]*il_lo, o_acc[j][1]*il_lo);
        *(__half2*)&Ob[(size_t)rh*Dz + c] =
            __floats2half2_rn(o_acc[j][2]*il_hi, o_acc[j][3]*il_hi);
    }
}

// ---------------- host orchestration ----------------
extern "C" void kernel_launch(void* const* d_in, const int* in_sizes, int n_in,
                              void* d_out, int out_size)
{
    const float* x     = (const float*)d_in[0];
    const float* kv    = (const float*)d_in[1];
    const int*   mask  = (const int*)  d_in[2];
    const float* ln1_g = (const float*)d_in[3];
    const float* ln1_b = (const float*)d_in[4];
    const float* qw[2] = { (const float*)d_in[5],  (const float*)d_in[10] };
    const float* kw[2] = { (const float*)d_in[6],  (const float*)d_in[11] };
    const float* vw[2] = { (const float*)d_in[7],  (const float*)d_in[12] };
    const float* ow[2] = { (const float*)d_in[8],  (const float*)d_in[13] };
    const float* ob[2] = { (const float*)d_in[9],  (const float*)d_in[14] };
    const float* ln2_g = (const float*)d_in[15];
    const float* ln2_b = (const float*)d_in[16];
    const float* w1    = (const float*)d_in[17];
    const float* b1    = (const float*)d_in[18];
    const float* w2    = (const float*)d_in[19];
    const float* b2    = (const float*)d_in[20];
    float* out = (float*)d_out;

    float *y, *q, *kvbuf, *x2;
    __half *y16, *kvn16, *o16, *yf16, *h16, *wth;
    cudaGetSymbolAddress((void**)&y,     g_y);
    cudaGetSymbolAddress((void**)&q,     g_q);
    cudaGetSymbolAddress((void**)&kvbuf, g_kv);
    cudaGetSymbolAddress((void**)&x2,    g_x2);
    cudaGetSymbolAddress((void**)&y16,   g_y16);
    cudaGetSymbolAddress((void**)&kvn16, g_kvn16);
    cudaGetSymbolAddress((void**)&o16,   g_o16);
    cudaGetSymbolAddress((void**)&yf16,  g_yf16);
    cudaGetSymbolAddress((void**)&h16,   g_h16);
    cudaGetSymbolAddress((void**)&wth,   g_wth);

    cudaFuncSetAttribute(flash_kernel,
        cudaFuncAttributeMaxDynamicSharedMemorySize, FLASH_SMEM);
    cudaFuncSetAttribute(hgemm,
        cudaFuncAttributeMaxDynamicSharedMemorySize, GEMM_SMEM);

    const int M = Bz * S1z;   // 4096
    const size_t MM = 1024 * 1024;

    __half* qwt[2] = { wth + 0*MM, wth + 1*MM };
    __half* owt[2] = { wth + 2*MM, wth + 3*MM };
    __half* kvwt   = wth + 4*MM;   // kw0^T | vw0^T | kw1^T | vw1^T  [4096,1024]
    __half* w1t    = wth + 8*MM;   // [4096,1024]
    __half* w2t    = wth + 12*MM;  // [1024,4096]

    dim3 tb(32, 8);
    transpose8_kernel<<<dim3(32,32,8), tb>>>(
        qw[0], qwt[0], qw[1], qwt[1], ow[0], owt[0], ow[1], owt[1],
        kw[0], kvwt + 0*MM, vw[0], kvwt + 1*MM, kw[1], kvwt + 2*MM, vw[1], kvwt + 3*MM);
    transpose_kernel<<<dim3(FFNz/32, Dz/32), tb>>>(w1, w1t, Dz, FFNz);
    transpose_kernel<<<dim3(Dz/32, FFNz/32), tb>>>(w2, w2t, FFNz, Dz);

    ln_kernel<<<Bz * S1z, 256>>>(x,  y,       y16,   ln1_g, ln1_b);
    ln_kernel<<<Bz * S2z, 256>>>(kv, nullptr, kvn16, ln1_g, ln1_b);

    dim3 gProj(Dz/128, M/128);      // (8, 32)
    dim3 gKV(4096/128, M/128);      // (32, 32)
    dim3 gFlash(S1z/128, Bz*Hz);    // (8, 64)
    dim3 gF1(FFNz/128, M/128);      // (32, 32)

    // all four K/V projections in one fp16 GEMM (kvn is layer-invariant)
    hgemm<<<gKV, 256, GEMM_SMEM>>>(Dz, kvn16, Dz, kvwt, Dz, kvbuf, nullptr, 4096,
        nullptr, nullptr, 0, 0);

    for (int l = 0; l < 2; l++) {
        hgemm<<<gProj, 256, GEMM_SMEM>>>(Dz, y16, Dz, qwt[l], Dz, q, nullptr, Dz,
            nullptr, nullptr, 0, 0);

        flash_kernel<<<gFlash, 256, FLASH_SMEM>>>(
            q, kvbuf + l*2048, kvbuf + l*2048 + 1024, 4096, mask, o16);

        // y = O @ ow + ob + y  (dual fp32 + fp16 outputs)
        hgemm<<<gProj, 256, GEMM_SMEM>>>(Dz, o16, Dz, owt[l], Dz, y, y16, Dz,
            ob[l], y, Dz, 0);
    }

    add_kernel<<<(M * Dz) / (256 * 4), 256>>>(x, y, x2);
    ln_kernel<<<M, 256>>>(x2, nullptr, yf16, ln2_g, ln2_b);

    // h = relu(y @ w1 + b1)  (fp16 output only — FFN2 is its sole consumer)
    hgemm<<<gF1, 256, GEMM_SMEM>>>(Dz, yf16, Dz, w1t, Dz, nullptr, h16, FFNz,
        b1, nullptr, 0, 1);

    // out = h @ w2 + b2 + x2
    hgemm<<<gProj, 256, GEMM_SMEM>>>(FFNz, h16, FFNz, w2t, FFNz, out, nullptr, Dz,
        b2, x2, Dz, 0);
}

// round 8
// speedup vs baseline: 1.7679x; 1.1395x over previous
#include <cuda_runtime.h>
#include <cuda_fp16.h>
#include <cstdint>
#include <math.h>

// Problem constants
#define Bz   4
#define S1z  1024
#define S2z  1024
#define Dz   1024
#define Hz   16
#define DKz  64
#define FFNz 4096

// ---------------- scratch ----------------
__device__ float  g_y   [Bz * S1z * Dz];
__device__ float  g_x2  [Bz * S1z * Dz];
__device__ __half g_y16  [Bz * S1z * Dz];
__device__ __half g_kvn16[Bz * S2z * Dz];
__device__ __half g_q16  [Bz * S1z * Dz];
__device__ __half g_kv16 [(size_t)Bz * S2z * 4096];  // k0|v0|k1|v1, ld=4096
__device__ __half g_o16  [Bz * S1z * Dz];
__device__ __half g_yf16 [Bz * S1z * Dz];
__device__ __half g_h16  [(size_t)Bz * S1z * FFNz];
__device__ __half g_wth  [16 * 1024 * 1024];

// ---------------- helpers ----------------
__device__ __forceinline__ uint32_t smem_u32(const void* p) {
    return (uint32_t)__cvta_generic_to_shared(p);
}
__device__ __forceinline__ void cp16(uint32_t dst, const void* src) {
    asm volatile("cp.async.cg.shared.global [%0], [%1], 16;" :: "r"(dst), "l"(src));
}
__device__ __forceinline__ void mma_f16(float* c, const uint32_t* a, const uint32_t* b) {
    asm volatile("mma.sync.aligned.m16n8k16.row.col.f32.f16.f16.f32 "
                 "{%0,%1,%2,%3},{%4,%5,%6,%7},{%8,%9},{%0,%1,%2,%3};"
                 : "+f"(c[0]), "+f"(c[1]), "+f"(c[2]), "+f"(c[3])
                 : "r"(a[0]), "r"(a[1]), "r"(a[2]), "r"(a[3]), "r"(b[0]), "r"(b[1]));
}
__device__ __forceinline__ void ldsm4(uint32_t* r, uint32_t addr) {
    asm volatile("ldmatrix.sync.aligned.m8n8.x4.shared.b16 {%0,%1,%2,%3}, [%4];"
                 : "=r"(r[0]), "=r"(r[1]), "=r"(r[2]), "=r"(r[3]) : "r"(addr));
}
__device__ __forceinline__ void ldsm4t(uint32_t* r, uint32_t addr) {
    asm volatile("ldmatrix.sync.aligned.m8n8.x4.trans.shared.b16 {%0,%1,%2,%3}, [%4];"
                 : "=r"(r[0]), "=r"(r[1]), "=r"(r[2]), "=r"(r[3]) : "r"(addr));
}

// ---------------- fp16 tensor-core GEMM --------------------------------------
// C = A[M,K] @ Bt^T ; A [M,K] fp16, Bt [N,K] fp16. CTA 128x128, 8 warps, BK=32.
#define HSTR 40
#define HSTAGE (256 * HSTR * 2)
#define GEMM_SMEM (3 * HSTAGE)

__global__ void __launch_bounds__(256)
hgemm(int K,
      const __half* __restrict__ A, int lda,
      const __half* __restrict__ Bt, int ldb,
      float* __restrict__ C32, __half* __restrict__ C16, int ldc,
      const float* __restrict__ bias,
      const float* __restrict__ res, int ldres, int relu)
{
    extern __shared__ __align__(16) char smc[];
    int tid = threadIdx.x;
    int bm = blockIdx.y * 128, bn = blockIdx.x * 128;
    int warp = tid >> 5, lane = tid & 31, g = lane >> 2, tg = lane & 3;
    int wn = warp & 1, wm = warp >> 1;

    uint32_t sb = smem_u32(smc);
    const int NT = K / 32;

    auto issue = [&](int t) {
        uint32_t base = sb + (uint32_t)((t % 3) * HSTAGE);
        #pragma unroll
        for (int i = 0; i < 2; i++) {
            int e = tid + i * 256, r = e >> 2, c = (e & 3) * 8;
            cp16(base + (uint32_t)(r * HSTR + c) * 2u,
                 A + (size_t)(bm + r) * lda + t * 32 + c);
        }
        #pragma unroll
        for (int i = 0; i < 2; i++) {
            int e = tid + i * 256, r = e >> 2, c = (e & 3) * 8;
            cp16(base + (uint32_t)((128 + r) * HSTR + c) * 2u,
                 Bt + (size_t)(bn + r) * ldb + t * 32 + c);
        }
        asm volatile("cp.async.commit_group;");
    };

    int q = lane >> 3, rr = lane & 7;
    uint32_t a_off[2][2];
    #pragma unroll
    for (int mi = 0; mi < 2; mi++)
        #pragma unroll
        for (int ks = 0; ks < 2; ks++)
            a_off[mi][ks] = (uint32_t)(((wm*32 + mi*16 + (q&1)*8 + rr) * HSTR
                                        + ks*16 + (q>>1)*8) * 2);
    uint32_t b_off[4][2];
    #pragma unroll
    for (int jp = 0; jp < 4; jp++)
        #pragma unroll
        for (int ks = 0; ks < 2; ks++)
            b_off[jp][ks] = (uint32_t)(((128 + wn*64 + jp*16 + (q>>1)*8 + rr) * HSTR
                                        + ks*16 + (q&1)*8) * 2);

    float acc[2][8][4] = {};

    issue(0);
    if (NT > 1) issue(1);

    for (int t = 0; t < NT; t++) {
        if (t + 1 < NT) asm volatile("cp.async.wait_group 1;");
        else            asm volatile("cp.async.wait_group 0;");
        __syncthreads();
        if (t + 2 < NT) issue(t + 2);

        uint32_t stage = sb + (uint32_t)((t % 3) * HSTAGE);
        #pragma unroll
        for (int ks = 0; ks < 2; ks++) {
            uint32_t a[2][4], b[4][4];
            #pragma unroll
            for (int mi = 0; mi < 2; mi++) ldsm4(a[mi], stage + a_off[mi][ks]);
            #pragma unroll
            for (int jp = 0; jp < 4; jp++) ldsm4(b[jp], stage + b_off[jp][ks]);
            #pragma unroll
            for (int mi = 0; mi < 2; mi++)
                #pragma unroll
                for (int jp = 0; jp < 4; jp++) {
                    mma_f16(acc[mi][jp*2],     a[mi], &b[jp][0]);
                    mma_f16(acc[mi][jp*2 + 1], a[mi], &b[jp][2]);
                }
        }
    }

    #pragma unroll
    for (int mi = 0; mi < 2; mi++) {
        #pragma unroll
        for (int j = 0; j < 8; j++) {
            int m0 = bm + wm*32 + mi*16 + g;
            int n0 = bn + wn*64 + j*8 + 2*tg;
            float v0 = acc[mi][j][0], v1 = acc[mi][j][1];
            float v2 = acc[mi][j][2], v3 = acc[mi][j][3];
            if (bias) {
                float b0 = bias[n0], b1 = bias[n0 + 1];
                v0 += b0; v1 += b1; v2 += b0; v3 += b1;
            }
            if (res) {
                v0 += res[(size_t)m0*ldres + n0];
                v1 += res[(size_t)m0*ldres + n0 + 1];
                v2 += res[(size_t)(m0 + 8)*ldres + n0];
                v3 += res[(size_t)(m0 + 8)*ldres + n0 + 1];
            }
            if (relu) {
                v0 = fmaxf(v0, 0.f); v1 = fmaxf(v1, 0.f);
                v2 = fmaxf(v2, 0.f); v3 = fmaxf(v3, 0.f);
            }
            if (C32) {
                *(float2*)&C32[(size_t)m0*ldc + n0]       = make_float2(v0, v1);
                *(float2*)&C32[(size_t)(m0 + 8)*ldc + n0] = make_float2(v2, v3);
            }
            if (C16) {
                *(__half2*)&C16[(size_t)m0*ldc + n0]       = __floats2half2_rn(v0, v1);
                *(__half2*)&C16[(size_t)(m0 + 8)*ldc + n0] = __floats2half2_rn(v2, v3);
            }
        }
    }
}

// ---------------- transpose + fp32->fp16 -------------------------------------
__global__ void transpose8_kernel(
    const float* s0, __half* d0, const float* s1, __half* d1,
    const float* s2, __half* d2, const float* s3, __half* d3,
    const float* s4, __half* d4, const float* s5, __half* d5,
    const float* s6, __half* d6, const float* s7, __half* d7)
{
    __shared__ float tile[32][33];
    const float* src; __half* dst;
    switch (blockIdx.z) {
        case 0: src = s0; dst = d0; break;
        case 1: src = s1; dst = d1; break;
        case 2: src = s2; dst = d2; break;
        case 3: src = s3; dst = d3; break;
        case 4: src = s4; dst = d4; break;
        case 5: src = s5; dst = d5; break;
        case 6: src = s6; dst = d6; break;
        default: src = s7; dst = d7; break;
    }
    int tx = threadIdx.x, ty = threadIdx.y;
    int c0 = blockIdx.x * 32, r0 = blockIdx.y * 32;
    #pragma unroll
    for (int j = 0; j < 32; j += 8)
        tile[ty + j][tx] = src[(size_t)(r0 + ty + j) * Dz + c0 + tx];
    __syncthreads();
    #pragma unroll
    for (int j = 0; j < 32; j += 8)
        dst[(size_t)(c0 + ty + j) * Dz + r0 + tx] = __float2half_rn(tile[tx][ty + j]);
}

__global__ void transpose_kernel(const float* __restrict__ src, __half* __restrict__ dst,
                                 int R, int C)
{
    __shared__ float tile[32][33];
    int tx = threadIdx.x, ty = threadIdx.y;
    int c0 = blockIdx.x * 32, r0 = blockIdx.y * 32;
    #pragma unroll
    for (int j = 0; j < 32; j += 8)
        tile[ty + j][tx] = src[(size_t)(r0 + ty + j) * C + c0 + tx];
    __syncthreads();
    #pragma unroll
    for (int j = 0; j < 32; j += 8)
        dst[(size_t)(c0 + ty + j) * R + r0 + tx] = __float2half_rn(tile[tx][ty + j]);
}

// ---------------- LayerNorm (optional add-input, dual outputs) ---------------
__global__ void ln_kernel(const float* __restrict__ in, const float* __restrict__ add,
                          float* __restrict__ sum32,
                          float* __restrict__ out32, __half* __restrict__ out16,
                          const float* __restrict__ g, const float* __restrict__ bta)
{
    size_t row = blockIdx.x;
    int tid = threadIdx.x;
    float4 v = ((const float4*)(in + row * (size_t)Dz))[tid];
    if (add) {
        float4 a4 = ((const float4*)(add + row * (size_t)Dz))[tid];
        v.x += a4.x; v.y += a4.y; v.z += a4.z; v.w += a4.w;
        if (sum32) ((float4*)(sum32 + row * (size_t)Dz))[tid] = v;
    }
    float s = v.x + v.y + v.z + v.w;
    float q = v.x*v.x + v.y*v.y + v.z*v.z + v.w*v.w;
    #pragma unroll
    for (int o = 16; o; o >>= 1) {
        s += __shfl_xor_sync(0xffffffffu, s, o);
        q += __shfl_xor_sync(0xffffffffu, q, o);
    }
    __shared__ float ss[8], qq[8];
    int lane = tid & 31, wid = tid >> 5;
    if (!lane) { ss[wid] = s; qq[wid] = q; }
    __syncthreads();
    if (tid < 32) {
        s = (tid < 8) ? ss[tid] : 0.f;
        q = (tid < 8) ? qq[tid] : 0.f;
        #pragma unroll
        for (int o = 4; o; o >>= 1) {
            s += __shfl_xor_sync(0xffffffffu, s, o);
            q += __shfl_xor_sync(0xffffffffu, q, o);
        }
        if (!tid) { ss[0] = s; qq[0] = q; }
    }
    __syncthreads();
    float mean = ss[0] * (1.f / Dz);
    float var  = qq[0] * (1.f / Dz) - mean * mean;
    float inv  = rsqrtf(var + 1e-5f);
    float4 gv = ((const float4*)g)[tid];
    float4 bv = ((const float4*)bta)[tid];
    float4 o4;
    o4.x = (v.x - mean) * inv * gv.x + bv.x;
    o4.y = (v.y - mean) * inv * gv.y + bv.y;
    o4.z = (v.z - mean) * inv * gv.z + bv.z;
    o4.w = (v.w - mean) * inv * gv.w + bv.w;
    if (out32) ((float4*)(out32 + row * (size_t)Dz))[tid] = o4;
    if (out16) {
        __half2 h0 = __floats2half2_rn(o4.x, o4.y);
        __half2 h1 = __floats2half2_rn(o4.z, o4.w);
        uint2 u = make_uint2(*(uint32_t*)&h0, *(uint32_t*)&h1);
        ((uint2*)(out16 + row * (size_t)Dz))[tid] = u;
    }
}

// ---------------- fused fp16 flash cross-attention ---------------------------
// Q [m,64] fp16 frags in regs; K/V tiles [64 x 64] fp16 SMEM, double-buffered;
// S and P·V via m16n8k16; P staged fp16; V B-frags via ldmatrix.trans.
#define FSTR 72   // halves per SMEM row (64 + 8 pad; 144B, 16B-aligned, LDSM-conflict-free)
#define FLASH_SMEM ((2*64*FSTR + 2*64*FSTR + 128*FSTR) * 2 + S2z * 4)

__global__ void __launch_bounds__(256)
flash16_kernel(const __half* __restrict__ Q, const __half* __restrict__ Kg,
               const __half* __restrict__ Vg, int ldkv,
               const int* __restrict__ mask, __half* __restrict__ O16)
{
    extern __shared__ char smc[];
    __half* Ks = (__half*)smc;
    __half* Vs = Ks + 2*64*FSTR;
    __half* Ps = Vs + 2*64*FSTR;
    float*  Mf = (float*)(Ps + 128*FSTR);

    int bh = blockIdx.y;
    int b = bh / Hz, h = bh % Hz;
    int q0 = blockIdx.x * 128;
    int tid = threadIdx.x, warp = tid >> 5, lane = tid & 31, g = lane >> 2, tg = lane & 3;
    int q2 = lane >> 3, rr = lane & 7;

    const __half* Qb = Q  + ((size_t)(b*S1z + q0))*Dz + h*DKz;
    const __half* Kb = Kg + (size_t)b*S2z*ldkv + h*DKz;
    const __half* Vb = Vg + (size_t)b*S2z*ldkv + h*DKz;

    for (int i = tid; i < S2z; i += 256) Mf[i] = mask[(size_t)b*S2z + i] ? 1.f : 0.f;

    // Q fragments (m16n8k16 A layout) straight from global
    uint32_t qa[4][4];
    {
        int ml = warp*16 + g, mh = ml + 8;
        #pragma unroll
        for (int ki = 0; ki < 4; ki++) {
            qa[ki][0] = *(const uint32_t*)&Qb[(size_t)ml*Dz + ki*16 + tg*2];
            qa[ki][1] = *(const uint32_t*)&Qb[(size_t)mh*Dz + ki*16 + tg*2];
            qa[ki][2] = *(const uint32_t*)&Qb[(size_t)ml*Dz + ki*16 + 8 + tg*2];
            qa[ki][3] = *(const uint32_t*)&Qb[(size_t)mh*Dz + ki*16 + 8 + tg*2];
        }
    }

    uint32_t ksb = smem_u32(Ks), vsb = smem_u32(Vs), psb = smem_u32(Ps);

    auto issue = [&](int t) {
        int buf = t & 1;
        #pragma unroll
        for (int i = 0; i < 2; i++) {          // 64 rows x 8 chunks of 8 halves
            int e = tid + i*256, r = e >> 3, c = (e & 7) * 8;
            cp16(ksb + (uint32_t)(buf*64*FSTR + r*FSTR + c)*2u,
                 Kb + (size_t)(t*64 + r)*ldkv + c);
        }
        #pragma unroll
        for (int i = 0; i < 2; i++) {
            int e = tid + i*256, r = e >> 3, c = (e & 7) * 8;
            cp16(vsb + (uint32_t)(buf*64*FSTR + r*FSTR + c)*2u,
                 Vb + (size_t)(t*64 + r)*ldkv + c);
        }
        asm volatile("cp.async.commit_group;");
    };

    // LDSM offsets (bytes)
    uint32_t kb_off[4][4];   // [n-octet-pair jp][ki]: K [n][k], no-trans
    #pragma unroll
    for (int jp = 0; jp < 4; jp++)
        #pragma unroll
        for (int ki = 0; ki < 4; ki++)
            kb_off[jp][ki] = (uint32_t)(((jp*16 + (q2>>1)*8 + rr) * FSTR
                                         + ki*16 + (q2&1)*8) * 2);
    uint32_t pa_off[4];      // P A-frags [m][k], no-trans
    #pragma unroll
    for (int ki = 0; ki < 4; ki++)
        pa_off[ki] = (uint32_t)(((warp*16 + (q2&1)*8 + rr) * FSTR
                                 + ki*16 + (q2>>1)*8) * 2);
    uint32_t vb_off[4][4];   // V [k][n], trans -> B frags
    #pragma unroll
    for (int ki = 0; ki < 4; ki++)
        #pragma unroll
        for (int jp = 0; jp < 4; jp++)
            vb_off[ki][jp] = (uint32_t)(((ki*16 + (q2&1)*8 + rr) * FSTR
                                         + jp*16 + (q2>>1)*8) * 2);

    float s_acc[8][4];
    float o_acc[8][4] = {};
    float m_lo = -INFINITY, m_hi = -INFINITY, l_lo = 0.f, l_hi = 0.f;
    int rl = warp*16 + g, rh = rl + 8;

    issue(0);
    for (int t = 0; t < S2z/64; t++) {
        if (t + 1 < S2z/64) { issue(t + 1); asm volatile("cp.async.wait_group 1;"); }
        else                { asm volatile("cp.async.wait_group 0;"); }
        __syncthreads();
        int buf = t & 1;
        uint32_t kbase = ksb + (uint32_t)(buf*64*FSTR)*2u;
        uint32_t vbase = vsb + (uint32_t)(buf*64*FSTR)*2u;

        // ---- S = Q @ K^T ----
        #pragma unroll
        for (int j = 0; j < 8; j++)
            s_acc[j][0] = s_acc[j][1] = s_acc[j][2] = s_acc[j][3] = 0.f;
        #pragma unroll
        for (int ki = 0; ki < 4; ki++) {
            uint32_t bf[4][4];
            #pragma unroll
            for (int jp = 0; jp < 4; jp++) ldsm4(bf[jp], kbase + kb_off[jp][ki]);
            #pragma unroll
            for (int jp = 0; jp < 4; jp++) {
                mma_f16(s_acc[jp*2],     qa[ki], &bf[jp][0]);
                mma_f16(s_acc[jp*2 + 1], qa[ki], &bf[jp][2]);
            }
        }

        // ---- mask + scale + online softmax ----
        float rmax_lo = -INFINITY, rmax_hi = -INFINITY;
        #pragma unroll
        for (int j = 0; j < 8; j++) {
            int c0 = t*64 + j*8 + 2*tg;
            float mf0 = Mf[c0], mf1 = Mf[c0 + 1];
            s_acc[j][0] = (mf0 != 0.f) ? s_acc[j][0]*0.125f : -1e9f;
            s_acc[j][1] = (mf1 != 0.f) ? s_acc[j][1]*0.125f : -1e9f;
            s_acc[j][2] = (mf0 != 0.f) ? s_acc[j][2]*0.125f : -1e9f;
            s_acc[j][3] = (mf1 != 0.f) ? s_acc[j][3]*0.125f : -1e9f;
            rmax_lo = fmaxf(rmax_lo, fmaxf(s_acc[j][0], s_acc[j][1]));
            rmax_hi = fmaxf(rmax_hi, fmaxf(s_acc[j][2], s_acc[j][3]));
        }
        rmax_lo = fmaxf(rmax_lo, __shfl_xor_sync(0xffffffffu, rmax_lo, 1));
        rmax_lo = fmaxf(rmax_lo, __shfl_xor_sync(0xffffffffu, rmax_lo, 2));
        rmax_hi = fmaxf(rmax_hi, __shfl_xor_sync(0xffffffffu, rmax_hi, 1));
        rmax_hi = fmaxf(rmax_hi, __shfl_xor_sync(0xffffffffu, rmax_hi, 2));
        float mn_lo = fmaxf(m_lo, rmax_lo), mn_hi = fmaxf(m_hi, rmax_hi);
        float al_lo = __expf(m_lo - mn_lo), al_hi = __expf(m_hi - mn_hi);
        m_lo = mn_lo; m_hi = mn_hi;

        float sum_lo = 0.f, sum_hi = 0.f;
        #pragma unroll
        for (int j = 0; j < 8; j++) {
            float p0 = __expf(s_acc[j][0] - mn_lo);
            float p1 = __expf(s_acc[j][1] - mn_lo);
            float p2 = __expf(s_acc[j][2] - mn_hi);
            float p3 = __expf(s_acc[j][3] - mn_hi);
            sum_lo += p0 + p1; sum_hi += p2 + p3;
            int c = j*8 + 2*tg;
            *(__half2*)&Ps[rl*FSTR + c] = __floats2half2_rn(p0, p1);
            *(__half2*)&Ps[rh*FSTR + c] = __floats2half2_rn(p2, p3);
        }
        sum_lo += __shfl_xor_sync(0xffffffffu, sum_lo, 1);
        sum_lo += __shfl_xor_sync(0xffffffffu, sum_lo, 2);
        sum_hi += __shfl_xor_sync(0xffffffffu, sum_hi, 1);
        sum_hi += __shfl_xor_sync(0xffffffffu, sum_hi, 2);
        l_lo = al_lo*l_lo + sum_lo;
        l_hi = al_hi*l_hi + sum_hi;
        #pragma unroll
        for (int j = 0; j < 8; j++) {
            o_acc[j][0] *= al_lo; o_acc[j][1] *= al_lo;
            o_acc[j][2] *= al_hi; o_acc[j][3] *= al_hi;
        }
        __syncwarp();   // Ps rows are per-warp; order STS before LDSM

        // ---- O += P @ V ----
        #pragma unroll
        for (int ki = 0; ki < 4; ki++) {
            uint32_t pa[4];
            ldsm4(pa, psb + pa_off[ki]);
            #pragma unroll
            for (int jp = 0; jp < 4; jp++) {
                uint32_t vb[4];
                ldsm4t(vb, vbase + vb_off[ki][jp]);
                mma_f16(o_acc[jp*2],     pa, &vb[0]);
                mma_f16(o_acc[jp*2 + 1], pa, &vb[2]);
            }
        }
        __syncthreads();   // all warps done with K/V buffer before re-fill
    }

    float il_lo = 1.f / l_lo, il_hi = 1.f / l_hi;
    __half* Ob = O16 + ((size_t)(b*S1z + q0))*Dz + h*DKz;
    #pragma unroll
    for (int j = 0; j < 8; j++) {
        int c = j*8 + 2*tg;
        *(__half2*)&Ob[(size_t)rl*Dz + c] =
            __floats2half2_rn(o_acc[j][0]*il_lo, o_acc[j][1]*il_lo);
        *(__half2*)&Ob[(size_t)rh*Dz + c] =
            __floats2half2_rn(o_acc[j][2]*il_hi, o_acc[j][3]*il_hi);
    }
}

// ---------------- host orchestration ----------------
extern "C" void kernel_launch(void* const* d_in, const int* in_sizes, int n_in,
                              void* d_out, int out_size)
{
    const float* x     = (const float*)d_in[0];
    const float* kv    = (const float*)d_in[1];
    const int*   mask  = (const int*)  d_in[2];
    const float* ln1_g = (const float*)d_in[3];
    const float* ln1_b = (const float*)d_in[4];
    const float* qw[2] = { (const float*)d_in[5],  (const float*)d_in[10] };
    const float* kw[2] = { (const float*)d_in[6],  (const float*)d_in[11] };
    const float* vw[2] = { (const float*)d_in[7],  (const float*)d_in[12] };
    const float* ow[2] = { (const float*)d_in[8],  (const float*)d_in[13] };
    const float* ob[2] = { (const float*)d_in[9],  (const float*)d_in[14] };
    const float* ln2_g = (const float*)d_in[15];
    const float* ln2_b = (const float*)d_in[16];
    const float* w1    = (const float*)d_in[17];
    const float* b1    = (const float*)d_in[18];
    const float* w2    = (const float*)d_in[19];
    const float* b2    = (const float*)d_in[20];
    float* out = (float*)d_out;

    float *y, *x2;
    __half *y16, *kvn16, *q16, *kv16, *o16, *yf16, *h16, *wth;
    cudaGetSymbolAddress((void**)&y,     g_y);
    cudaGetSymbolAddress((void**)&x2,    g_x2);
    cudaGetSymbolAddress((void**)&y16,   g_y16);
    cudaGetSymbolAddress((void**)&kvn16, g_kvn16);
    cudaGetSymbolAddress((void**)&q16,   g_q16);
    cudaGetSymbolAddress((void**)&kv16,  g_kv16);
    cudaGetSymbolAddress((void**)&o16,   g_o16);
    cudaGetSymbolAddress((void**)&yf16,  g_yf16);
    cudaGetSymbolAddress((void**)&h16,   g_h16);
    cudaGetSymbolAddress((void**)&wth,   g_wth);

    cudaFuncSetAttribute(flash16_kernel,
        cudaFuncAttributeMaxDynamicSharedMemorySize, FLASH_SMEM);
    cudaFuncSetAttribute(hgemm,
        cudaFuncAttributeMaxDynamicSharedMemorySize, GEMM_SMEM);

    const int M = Bz * S1z;   // 4096
    const size_t MM = 1024 * 1024;

    __half* qwt[2] = { wth + 0*MM, wth + 1*MM };
    __half* owt[2] = { wth + 2*MM, wth + 3*MM };
    __half* kvwt   = wth + 4*MM;
    __half* w1t    = wth + 8*MM;
    __half* w2t    = wth + 12*MM;

    dim3 tb(32, 8);
    transpose8_kernel<<<dim3(32,32,8), tb>>>(
        qw[0], qwt[0], qw[1], qwt[1], ow[0], owt[0], ow[1], owt[1],
        kw[0], kvwt + 0*MM, vw[0], kvwt + 1*MM, kw[1], kvwt + 2*MM, vw[1], kvwt + 3*MM);
    transpose_kernel<<<dim3(FFNz/32, Dz/32), tb>>>(w1, w1t, Dz, FFNz);
    transpose_kernel<<<dim3(Dz/32, FFNz/32), tb>>>(w2, w2t, FFNz, Dz);

    ln_kernel<<<Bz * S1z, 256>>>(x,  nullptr, nullptr, y,       y16,   ln1_g, ln1_b);
    ln_kernel<<<Bz * S2z, 256>>>(kv, nullptr, nullptr, nullptr, kvn16, ln1_g, ln1_b);

    dim3 gProj(Dz/128, M/128);
    dim3 gKV(4096/128, M/128);
    dim3 gFlash(S1z/128, Bz*Hz);
    dim3 gF1(FFNz/128, M/128);

    // all four K/V projections in one fp16 GEMM -> fp16 KV buffer
    hgemm<<<gKV, 256, GEMM_SMEM>>>(Dz, kvn16, Dz, kvwt, Dz, nullptr, kv16, 4096,
        nullptr, nullptr, 0, 0);

    for (int l = 0; l < 2; l++) {
        hgemm<<<gProj, 256, GEMM_SMEM>>>(Dz, y16, Dz, qwt[l], Dz, nullptr, q16, Dz,
            nullptr, nullptr, 0, 0);

        flash16_kernel<<<gFlash, 256, FLASH_SMEM>>>(
            q16, kv16 + l*2048, kv16 + l*2048 + 1024, 4096, mask, o16);

        hgemm<<<gProj, 256, GEMM_SMEM>>>(Dz, o16, Dz, owt[l], Dz, y, y16, Dz,
            ob[l], y, Dz, 0);
    }

    // x2 = x + y ; yf16 = LN(x2)  (fused)
    ln_kernel<<<M, 256>>>(y, x, x2, nullptr, yf16, ln2_g, ln2_b);

    hgemm<<<gF1, 256, GEMM_SMEM>>>(Dz, yf16, Dz, w1t, Dz, nullptr, h16, FFNz,
        b1, nullptr, 0, 1);

    hgemm<<<gProj, 256, GEMM_SMEM>>>(FFNz, h16, FFNz, w2t, FFNz, out, nullptr, Dz,
        b2, x2, Dz, 0);
}

// round 9
// speedup vs baseline: 1.8831x; 1.0652x over previous
#include <cuda_runtime.h>
#include <cuda_fp16.h>
#include <cstdint>
#include <math.h>

// Problem constants
#define Bz   4
#define S1z  1024
#define S2z  1024
#define Dz   1024
#define Hz   16
#define DKz  64
#define FFNz 4096

// ---------------- scratch ----------------
__device__ float  g_y   [Bz * S1z * Dz];
__device__ float  g_x2  [Bz * S1z * Dz];
__device__ __half g_y16  [Bz * S1z * Dz];
__device__ __half g_kvn16[Bz * S2z * Dz];
__device__ __half g_q16  [Bz * S1z * Dz];
__device__ __half g_kv16 [(size_t)Bz * S2z * 4096];  // k0|v0|k1|v1, ld=4096
__device__ __half g_o16  [Bz * S1z * Dz];
__device__ __half g_yf16 [Bz * S1z * Dz];
__device__ __half g_h16  [(size_t)Bz * S1z * FFNz];
__device__ __half g_wth  [16 * 1024 * 1024];

// ---------------- helpers ----------------
__device__ __forceinline__ uint32_t smem_u32(const void* p) {
    return (uint32_t)__cvta_generic_to_shared(p);
}
__device__ __forceinline__ void cp16(uint32_t dst, const void* src) {
    asm volatile("cp.async.cg.shared.global [%0], [%1], 16;" :: "r"(dst), "l"(src));
}
__device__ __forceinline__ void mma_f16(float* c, const uint32_t* a, const uint32_t* b) {
    asm volatile("mma.sync.aligned.m16n8k16.row.col.f32.f16.f16.f32 "
                 "{%0,%1,%2,%3},{%4,%5,%6,%7},{%8,%9},{%0,%1,%2,%3};"
                 : "+f"(c[0]), "+f"(c[1]), "+f"(c[2]), "+f"(c[3])
                 : "r"(a[0]), "r"(a[1]), "r"(a[2]), "r"(a[3]), "r"(b[0]), "r"(b[1]));
}
__device__ __forceinline__ void ldsm4(uint32_t* r, uint32_t addr) {
    asm volatile("ldmatrix.sync.aligned.m8n8.x4.shared.b16 {%0,%1,%2,%3}, [%4];"
                 : "=r"(r[0]), "=r"(r[1]), "=r"(r[2]), "=r"(r[3]) : "r"(addr));
}
__device__ __forceinline__ void ldsm4t(uint32_t* r, uint32_t addr) {
    asm volatile("ldmatrix.sync.aligned.m8n8.x4.trans.shared.b16 {%0,%1,%2,%3}, [%4];"
                 : "=r"(r[0]), "=r"(r[1]), "=r"(r[2]), "=r"(r[3]) : "r"(addr));
}
__device__ __forceinline__ uint32_t h2pack(float a, float b) {
    __half2 h = __floats2half2_rn(a, b);
    return *(uint32_t*)&h;
}

// ---------------- fp16 tensor-core GEMM (unchanged, at mma.sync ceiling) -----
#define HSTR 40
#define HSTAGE (256 * HSTR * 2)
#define GEMM_SMEM (3 * HSTAGE)

__global__ void __launch_bounds__(256)
hgemm(int K,
      const __half* __restrict__ A, int lda,
      const __half* __restrict__ Bt, int ldb,
      float* __restrict__ C32, __half* __restrict__ C16, int ldc,
      const float* __restrict__ bias,
      const float* __restrict__ res, int ldres, int relu)
{
    extern __shared__ __align__(16) char smc[];
    int tid = threadIdx.x;
    int bm = blockIdx.y * 128, bn = blockIdx.x * 128;
    int warp = tid >> 5, lane = tid & 31, g = lane >> 2, tg = lane & 3;
    int wn = warp & 1, wm = warp >> 1;

    uint32_t sb = smem_u32(smc);
    const int NT = K / 32;

    auto issue = [&](int t) {
        uint32_t base = sb + (uint32_t)((t % 3) * HSTAGE);
        #pragma unroll
        for (int i = 0; i < 2; i++) {
            int e = tid + i * 256, r = e >> 2, c = (e & 3) * 8;
            cp16(base + (uint32_t)(r * HSTR + c) * 2u,
                 A + (size_t)(bm + r) * lda + t * 32 + c);
        }
        #pragma unroll
        for (int i = 0; i < 2; i++) {
            int e = tid + i * 256, r = e >> 2, c = (e & 3) * 8;
            cp16(base + (uint32_t)((128 + r) * HSTR + c) * 2u,
                 Bt + (size_t)(bn + r) * ldb + t * 32 + c);
        }
        asm volatile("cp.async.commit_group;");
    };

    int q = lane >> 3, rr = lane & 7;
    uint32_t a_off[2][2];
    #pragma unroll
    for (int mi = 0; mi < 2; mi++)
        #pragma unroll
        for (int ks = 0; ks < 2; ks++)
            a_off[mi][ks] = (uint32_t)(((wm*32 + mi*16 + (q&1)*8 + rr) * HSTR
                                        + ks*16 + (q>>1)*8) * 2);
    uint32_t b_off[4][2];
    #pragma unroll
    for (int jp = 0; jp < 4; jp++)
        #pragma unroll
        for (int ks = 0; ks < 2; ks++)
            b_off[jp][ks] = (uint32_t)(((128 + wn*64 + jp*16 + (q>>1)*8 + rr) * HSTR
                                        + ks*16 + (q&1)*8) * 2);

    float acc[2][8][4] = {};

    issue(0);
    if (NT > 1) issue(1);

    for (int t = 0; t < NT; t++) {
        if (t + 1 < NT) asm volatile("cp.async.wait_group 1;");
        else            asm volatile("cp.async.wait_group 0;");
        __syncthreads();
        if (t + 2 < NT) issue(t + 2);

        uint32_t stage = sb + (uint32_t)((t % 3) * HSTAGE);
        #pragma unroll
        for (int ks = 0; ks < 2; ks++) {
            uint32_t a[2][4], b[4][4];
            #pragma unroll
            for (int mi = 0; mi < 2; mi++) ldsm4(a[mi], stage + a_off[mi][ks]);
            #pragma unroll
            for (int jp = 0; jp < 4; jp++) ldsm4(b[jp], stage + b_off[jp][ks]);
            #pragma unroll
            for (int mi = 0; mi < 2; mi++)
                #pragma unroll
                for (int jp = 0; jp < 4; jp++) {
                    mma_f16(acc[mi][jp*2],     a[mi], &b[jp][0]);
                    mma_f16(acc[mi][jp*2 + 1], a[mi], &b[jp][2]);
                }
        }
    }

    #pragma unroll
    for (int mi = 0; mi < 2; mi++) {
        #pragma unroll
        for (int j = 0; j < 8; j++) {
            int m0 = bm + wm*32 + mi*16 + g;
            int n0 = bn + wn*64 + j*8 + 2*tg;
            float v0 = acc[mi][j][0], v1 = acc[mi][j][1];
            float v2 = acc[mi][j][2], v3 = acc[mi][j][3];
            if (bias) {
                float b0 = bias[n0], b1 = bias[n0 + 1];
                v0 += b0; v1 += b1; v2 += b0; v3 += b1;
            }
            if (res) {
                v0 += res[(size_t)m0*ldres + n0];
                v1 += res[(size_t)m0*ldres + n0 + 1];
                v2 += res[(size_t)(m0 + 8)*ldres + n0];
                v3 += res[(size_t)(m0 + 8)*ldres + n0 + 1];
            }
            if (relu) {
                v0 = fmaxf(v0, 0.f); v1 = fmaxf(v1, 0.f);
                v2 = fmaxf(v2, 0.f); v3 = fmaxf(v3, 0.f);
            }
            if (C32) {
                *(float2*)&C32[(size_t)m0*ldc + n0]       = make_float2(v0, v1);
                *(float2*)&C32[(size_t)(m0 + 8)*ldc + n0] = make_float2(v2, v3);
            }
            if (C16) {
                *(__half2*)&C16[(size_t)m0*ldc + n0]       = __floats2half2_rn(v0, v1);
                *(__half2*)&C16[(size_t)(m0 + 8)*ldc + n0] = __floats2half2_rn(v2, v3);
            }
        }
    }
}

// ---------------- transpose + fp32->fp16 -------------------------------------
__global__ void transpose8_kernel(
    const float* s0, __half* d0, const float* s1, __half* d1,
    const float* s2, __half* d2, const float* s3, __half* d3,
    const float* s4, __half* d4, const float* s5, __half* d5,
    const float* s6, __half* d6, const float* s7, __half* d7)
{
    __shared__ float tile[32][33];
    const float* src; __half* dst;
    switch (blockIdx.z) {
        case 0: src = s0; dst = d0; break;
        case 1: src = s1; dst = d1; break;
        case 2: src = s2; dst = d2; break;
        case 3: src = s3; dst = d3; break;
        case 4: src = s4; dst = d4; break;
        case 5: src = s5; dst = d5; break;
        case 6: src = s6; dst = d6; break;
        default: src = s7; dst = d7; break;
    }
    int tx = threadIdx.x, ty = threadIdx.y;
    int c0 = blockIdx.x * 32, r0 = blockIdx.y * 32;
    #pragma unroll
    for (int j = 0; j < 32; j += 8)
        tile[ty + j][tx] = src[(size_t)(r0 + ty + j) * Dz + c0 + tx];
    __syncthreads();
    #pragma unroll
    for (int j = 0; j < 32; j += 8)
        dst[(size_t)(c0 + ty + j) * Dz + r0 + tx] = __float2half_rn(tile[tx][ty + j]);
}

__global__ void transpose_kernel(const float* __restrict__ src, __half* __restrict__ dst,
                                 int R, int C)
{
    __shared__ float tile[32][33];
    int tx = threadIdx.x, ty = threadIdx.y;
    int c0 = blockIdx.x * 32, r0 = blockIdx.y * 32;
    #pragma unroll
    for (int j = 0; j < 32; j += 8)
        tile[ty + j][tx] = src[(size_t)(r0 + ty + j) * C + c0 + tx];
    __syncthreads();
    #pragma unroll
    for (int j = 0; j < 32; j += 8)
        dst[(size_t)(c0 + ty + j) * R + r0 + tx] = __float2half_rn(tile[tx][ty + j]);
}

// ---------------- LayerNorm core ----------------------------------------------
__device__ __forceinline__ void ln_row(float4 v,
                                       float* out32, __half* out16, size_t row, int tid,
                                       const float* __restrict__ g,
                                       const float* __restrict__ bta)
{
    float s = v.x + v.y + v.z + v.w;
    float q = v.x*v.x + v.y*v.y + v.z*v.z + v.w*v.w;
    #pragma unroll
    for (int o = 16; o; o >>= 1) {
        s += __shfl_xor_sync(0xffffffffu, s, o);
        q += __shfl_xor_sync(0xffffffffu, q, o);
    }
    __shared__ float ss[8], qq[8];
    int lane = tid & 31, wid = tid >> 5;
    if (!lane) { ss[wid] = s; qq[wid] = q; }
    __syncthreads();
    if (tid < 32) {
        s = (tid < 8) ? ss[tid] : 0.f;
        q = (tid < 8) ? qq[tid] : 0.f;
        #pragma unroll
        for (int o = 4; o; o >>= 1) {
            s += __shfl_xor_sync(0xffffffffu, s, o);
            q += __shfl_xor_sync(0xffffffffu, q, o);
        }
        if (!tid) { ss[0] = s; qq[0] = q; }
    }
    __syncthreads();
    float mean = ss[0] * (1.f / Dz);
    float var  = qq[0] * (1.f / Dz) - mean * mean;
    float inv  = rsqrtf(var + 1e-5f);
    float4 gv = ((const float4*)g)[tid];
    float4 bv = ((const float4*)bta)[tid];
    float4 o4;
    o4.x = (v.x - mean) * inv * gv.x + bv.x;
    o4.y = (v.y - mean) * inv * gv.y + bv.y;
    o4.z = (v.z - mean) * inv * gv.z + bv.z;
    o4.w = (v.w - mean) * inv * gv.w + bv.w;
    if (out32) ((float4*)(out32 + row * (size_t)Dz))[tid] = o4;
    if (out16) {
        __half2 h0 = __floats2half2_rn(o4.x, o4.y);
        __half2 h1 = __floats2half2_rn(o4.z, o4.w);
        uint2 u = make_uint2(*(uint32_t*)&h0, *(uint32_t*)&h1);
        ((uint2*)(out16 + row * (size_t)Dz))[tid] = u;
    }
}

// fused LN over x (rows 0..4095 -> y32,y16) and kv (rows 4096.. -> kvn16)
__global__ void ln_dual_kernel(const float* __restrict__ x, const float* __restrict__ kv,
                               float* __restrict__ y32, __half* __restrict__ y16,
                               __half* __restrict__ kvn16,
                               const float* __restrict__ g, const float* __restrict__ bta)
{
    int tid = threadIdx.x;
    if (blockIdx.x < Bz * S1z) {
        size_t row = blockIdx.x;
        float4 v = ((const float4*)(x + row * (size_t)Dz))[tid];
        ln_row(v, y32, y16, row, tid, g, bta);
    } else {
        size_t row = blockIdx.x - Bz * S1z;
        float4 v = ((const float4*)(kv + row * (size_t)Dz))[tid];
        ln_row(v, nullptr, kvn16, row, tid, g, bta);
    }
}

// add + LN fused (x2 = in + add; out16 = LN(x2))
__global__ void ln_add_kernel(const float* __restrict__ in, const float* __restrict__ add,
                              float* __restrict__ sum32, __half* __restrict__ out16,
                              const float* __restrict__ g, const float* __restrict__ bta)
{
    size_t row = blockIdx.x;
    int tid = threadIdx.x;
    float4 v = ((const float4*)(in + row * (size_t)Dz))[tid];
    float4 a4 = ((const float4*)(add + row * (size_t)Dz))[tid];
    v.x += a4.x; v.y += a4.y; v.z += a4.z; v.w += a4.w;
    ((float4*)(sum32 + row * (size_t)Dz))[tid] = v;
    ln_row(v, nullptr, out16, row, tid, g, bta);
}

// ---------------- fused fp16 flash cross-attention (register-direct P) -------
#define FSTR 72
#define FLASH_SMEM ((2*64*FSTR + 2*64*FSTR) * 2 + S2z * 4)

__global__ void __launch_bounds__(256)
flash16_kernel(const __half* __restrict__ Q, const __half* __restrict__ Kg,
               const __half* __restrict__ Vg, int ldkv,
               const int* __restrict__ mask, __half* __restrict__ O16)
{
    extern __shared__ char smc[];
    __half* Ks = (__half*)smc;
    __half* Vs = Ks + 2*64*FSTR;
    float*  Mf = (float*)(Vs + 2*64*FSTR);

    int bh = blockIdx.y;
    int b = bh / Hz, h = bh % Hz;
    int q0 = blockIdx.x * 128;
    int tid = threadIdx.x, warp = tid >> 5, lane = tid & 31, g = lane >> 2, tg = lane & 3;
    int q2 = lane >> 3, rr = lane & 7;

    const __half* Qb = Q  + ((size_t)(b*S1z + q0))*Dz + h*DKz;
    const __half* Kb = Kg + (size_t)b*S2z*ldkv + h*DKz;
    const __half* Vb = Vg + (size_t)b*S2z*ldkv + h*DKz;

    for (int i = tid; i < S2z; i += 256) Mf[i] = mask[(size_t)b*S2z + i] ? 1.f : 0.f;

    uint32_t qa[4][4];
    {
        int ml = warp*16 + g, mh = ml + 8;
        #pragma unroll
        for (int ki = 0; ki < 4; ki++) {
            qa[ki][0] = *(const uint32_t*)&Qb[(size_t)ml*Dz + ki*16 + tg*2];
            qa[ki][1] = *(const uint32_t*)&Qb[(size_t)mh*Dz + ki*16 + tg*2];
            qa[ki][2] = *(const uint32_t*)&Qb[(size_t)ml*Dz + ki*16 + 8 + tg*2];
            qa[ki][3] = *(const uint32_t*)&Qb[(size_t)mh*Dz + ki*16 + 8 + tg*2];
        }
    }

    uint32_t ksb = smem_u32(Ks), vsb = smem_u32(Vs);

    auto issue = [&](int t) {
        int buf = t & 1;
        #pragma unroll
        for (int i = 0; i < 2; i++) {
            int e = tid + i*256, r = e >> 3, c = (e & 7) * 8;
            cp16(ksb + (uint32_t)(buf*64*FSTR + r*FSTR + c)*2u,
                 Kb + (size_t)(t*64 + r)*ldkv + c);
        }
        #pragma unroll
        for (int i = 0; i < 2; i++) {
            int e = tid + i*256, r = e >> 3, c = (e & 7) * 8;
            cp16(vsb + (uint32_t)(buf*64*FSTR + r*FSTR + c)*2u,
                 Vb + (size_t)(t*64 + r)*ldkv + c);
        }
        asm volatile("cp.async.commit_group;");
    };

    uint32_t kb_off[4][4];   // K [n][k] no-trans B frags
    #pragma unroll
    for (int jp = 0; jp < 4; jp++)
        #pragma unroll
        for (int ki = 0; ki < 4; ki++)
            kb_off[jp][ki] = (uint32_t)(((jp*16 + (q2>>1)*8 + rr) * FSTR
                                         + ki*16 + (q2&1)*8) * 2);
    uint32_t vb_off[4][4];   // V [k][n] trans B frags
    #pragma unroll
    for (int ki = 0; ki < 4; ki++)
        #pragma unroll
        for (int jp = 0; jp < 4; jp++)
            vb_off[ki][jp] = (uint32_t)(((ki*16 + (q2&1)*8 + rr) * FSTR
                                         + jp*16 + (q2>>1)*8) * 2);

    float s_acc[8][4];
    float o_acc[8][4] = {};
    float m_lo = -INFINITY, m_hi = -INFINITY, l_lo = 0.f, l_hi = 0.f;
    int rl = warp*16 + g, rh = rl + 8;

    issue(0);
    for (int t = 0; t < S2z/64; t++) {
        if (t + 1 < S2z/64) { issue(t + 1); asm volatile("cp.async.wait_group 1;"); }
        else                { asm volatile("cp.async.wait_group 0;"); }
        __syncthreads();
        int buf = t & 1;
        uint32_t kbase = ksb + (uint32_t)(buf*64*FSTR)*2u;
        uint32_t vbase = vsb + (uint32_t)(buf*64*FSTR)*2u;

        // ---- S = Q @ K^T ----
        #pragma unroll
        for (int j = 0; j < 8; j++)
            s_acc[j][0] = s_acc[j][1] = s_acc[j][2] = s_acc[j][3] = 0.f;
        #pragma unroll
        for (int ki = 0; ki < 4; ki++) {
            uint32_t bf[4][4];
            #pragma unroll
            for (int jp = 0; jp < 4; jp++) ldsm4(bf[jp], kbase + kb_off[jp][ki]);
            #pragma unroll
            for (int jp = 0; jp < 4; jp++) {
                mma_f16(s_acc[jp*2],     qa[ki], &bf[jp][0]);
                mma_f16(s_acc[jp*2 + 1], qa[ki], &bf[jp][2]);
            }
        }

        // ---- mask + scale + online softmax (P stays in registers) ----
        float rmax_lo = -INFINITY, rmax_hi = -INFINITY;
        #pragma unroll
        for (int j = 0; j < 8; j++) {
            int c0 = t*64 + j*8 + 2*tg;
            float mf0 = Mf[c0], mf1 = Mf[c0 + 1];
            s_acc[j][0] = (mf0 != 0.f) ? s_acc[j][0]*0.125f : -1e9f;
            s_acc[j][1] = (mf1 != 0.f) ? s_acc[j][1]*0.125f : -1e9f;
            s_acc[j][2] = (mf0 != 0.f) ? s_acc[j][2]*0.125f : -1e9f;
            s_acc[j][3] = (mf1 != 0.f) ? s_acc[j][3]*0.125f : -1e9f;
            rmax_lo = fmaxf(rmax_lo, fmaxf(s_acc[j][0], s_acc[j][1]));
            rmax_hi = fmaxf(rmax_hi, fmaxf(s_acc[j][2], s_acc[j][3]));
        }
        rmax_lo = fmaxf(rmax_lo, __shfl_xor_sync(0xffffffffu, rmax_lo, 1));
        rmax_lo = fmaxf(rmax_lo, __shfl_xor_sync(0xffffffffu, rmax_lo, 2));
        rmax_hi = fmaxf(rmax_hi, __shfl_xor_sync(0xffffffffu, rmax_hi, 1));
        rmax_hi = fmaxf(rmax_hi, __shfl_xor_sync(0xffffffffu, rmax_hi, 2));
        float mn_lo = fmaxf(m_lo, rmax_lo), mn_hi = fmaxf(m_hi, rmax_hi);
        float al_lo = __expf(m_lo - mn_lo), al_hi = __expf(m_hi - mn_hi);
        m_lo = mn_lo; m_hi = mn_hi;

        float sum_lo = 0.f, sum_hi = 0.f;
        #pragma unroll
        for (int j = 0; j < 8; j++) {
            s_acc[j][0] = __expf(s_acc[j][0] - mn_lo);
            s_acc[j][1] = __expf(s_acc[j][1] - mn_lo);
            s_acc[j][2] = __expf(s_acc[j][2] - mn_hi);
            s_acc[j][3] = __expf(s_acc[j][3] - mn_hi);
            sum_lo += s_acc[j][0] + s_acc[j][1];
            sum_hi += s_acc[j][2] + s_acc[j][3];
        }
        sum_lo += __shfl_xor_sync(0xffffffffu, sum_lo, 1);
        sum_lo += __shfl_xor_sync(0xffffffffu, sum_lo, 2);
        sum_hi += __shfl_xor_sync(0xffffffffu, sum_hi, 1);
        sum_hi += __shfl_xor_sync(0xffffffffu, sum_hi, 2);
        l_lo = al_lo*l_lo + sum_lo;
        l_hi = al_hi*l_hi + sum_hi;
        #pragma unroll
        for (int j = 0; j < 8; j++) {
            o_acc[j][0] *= al_lo; o_acc[j][1] *= al_lo;
            o_acc[j][2] *= al_hi; o_acc[j][3] *= al_hi;
        }

        // ---- O += P @ V : P A-frags built directly from s_acc registers ----
        #pragma unroll
        for (int ki = 0; ki < 4; ki++) {
            uint32_t pa[4];
            pa[0] = h2pack(s_acc[2*ki    ][0], s_acc[2*ki    ][1]);
            pa[1] = h2pack(s_acc[2*ki    ][2], s_acc[2*ki    ][3]);
            pa[2] = h2pack(s_acc[2*ki + 1][0], s_acc[2*ki + 1][1]);
            pa[3] = h2pack(s_acc[2*ki + 1][2], s_acc[2*ki + 1][3]);
            #pragma unroll
            for (int jp = 0; jp < 4; jp++) {
                uint32_t vb[4];
                ldsm4t(vb, vbase + vb_off[ki][jp]);
                mma_f16(o_acc[jp*2],     pa, &vb[0]);
                mma_f16(o_acc[jp*2 + 1], pa, &vb[2]);
            }
        }
        __syncthreads();
    }

    float il_lo = 1.f / l_lo, il_hi = 1.f / l_hi;
    __half* Ob = O16 + ((size_t)(b*S1z + q0))*Dz + h*DKz;
    #pragma unroll
    for (int j = 0; j < 8; j++) {
        int c = j*8 + 2*tg;
        *(__half2*)&Ob[(size_t)rl*Dz + c] =
            __floats2half2_rn(o_acc[j][0]*il_lo, o_acc[j][1]*il_lo);
        *(__half2*)&Ob[(size_t)rh*Dz + c] =
            __floats2half2_rn(o_acc[j][2]*il_hi, o_acc[j][3]*il_hi);
    }
}

// ---------------- host orchestration ----------------
extern "C" void kernel_launch(void* const* d_in, const int* in_sizes, int n_in,
                              void* d_out, int out_size)
{
    const float* x     = (const float*)d_in[0];
    const float* kv    = (const float*)d_in[1];
    const int*   mask  = (const int*)  d_in[2];
    const float* ln1_g = (const float*)d_in[3];
    const float* ln1_b = (const float*)d_in[4];
    const float* qw[2] = { (const float*)d_in[5],  (const float*)d_in[10] };
    const float* kw[2] = { (const float*)d_in[6],  (const float*)d_in[11] };
    const float* vw[2] = { (const float*)d_in[7],  (const float*)d_in[12] };
    const float* ow[2] = { (const float*)d_in[8],  (const float*)d_in[13] };
    const float* ob[2] = { (const float*)d_in[9],  (const float*)d_in[14] };
    const float* ln2_g = (const float*)d_in[15];
    const float* ln2_b = (const float*)d_in[16];
    const float* w1    = (const float*)d_in[17];
    const float* b1    = (const float*)d_in[18];
    const float* w2    = (const float*)d_in[19];
    const float* b2    = (const float*)d_in[20];
    float* out = (float*)d_out;

    float *y, *x2;
    __half *y16, *kvn16, *q16, *kv16, *o16, *yf16, *h16, *wth;
    cudaGetSymbolAddress((void**)&y,     g_y);
    cudaGetSymbolAddress((void**)&x2,    g_x2);
    cudaGetSymbolAddress((void**)&y16,   g_y16);
    cudaGetSymbolAddress((void**)&kvn16, g_kvn16);
    cudaGetSymbolAddress((void**)&q16,   g_q16);
    cudaGetSymbolAddress((void**)&kv16,  g_kv16);
    cudaGetSymbolAddress((void**)&o16,   g_o16);
    cudaGetSymbolAddress((void**)&yf16,  g_yf16);
    cudaGetSymbolAddress((void**)&h16,   g_h16);
    cudaGetSymbolAddress((void**)&wth,   g_wth);

    cudaFuncSetAttribute(flash16_kernel,
        cudaFuncAttributeMaxDynamicSharedMemorySize, FLASH_SMEM);
    cudaFuncSetAttribute(hgemm,
        cudaFuncAttributeMaxDynamicSharedMemorySize, GEMM_SMEM);

    const int M = Bz * S1z;   // 4096
    const size_t MM = 1024 * 1024;

    __half* qwt[2] = { wth + 0*MM, wth + 1*MM };
    __half* owt[2] = { wth + 2*MM, wth + 3*MM };
    __half* kvwt   = wth + 4*MM;
    __half* w1t    = wth + 8*MM;
    __half* w2t    = wth + 12*MM;

    dim3 tb(32, 8);
    transpose8_kernel<<<dim3(32,32,8), tb>>>(
        qw[0], qwt[0], qw[1], qwt[1], ow[0], owt[0], ow[1], owt[1],
        kw[0], kvwt + 0*MM, vw[0], kvwt + 1*MM, kw[1], kvwt + 2*MM, vw[1], kvwt + 3*MM);
    transpose_kernel<<<dim3(FFNz/32, Dz/32), tb>>>(w1, w1t, Dz, FFNz);
    transpose_kernel<<<dim3(Dz/32, FFNz/32), tb>>>(w2, w2t, FFNz, Dz);

    // fused LN of x and kv in one launch
    ln_dual_kernel<<<Bz * (S1z + S2z), 256>>>(x, kv, y, y16, kvn16, ln1_g, ln1_b);

    dim3 gProj(Dz/128, M/128);
    dim3 gKV(4096/128, M/128);
    dim3 gFlash(S1z/128, Bz*Hz);
    dim3 gF1(FFNz/128, M/128);

    // all four K/V projections in one fp16 GEMM -> fp16 KV buffer
    hgemm<<<gKV, 256, GEMM_SMEM>>>(Dz, kvn16, Dz, kvwt, Dz, nullptr, kv16, 4096,
        nullptr, nullptr, 0, 0);

    for (int l = 0; l < 2; l++) {
        hgemm<<<gProj, 256, GEMM_SMEM>>>(Dz, y16, Dz, qwt[l], Dz, nullptr, q16, Dz,
            nullptr, nullptr, 0, 0);

        flash16_kernel<<<gFlash, 256, FLASH_SMEM>>>(
            q16, kv16 + l*2048, kv16 + l*2048 + 1024, 4096, mask, o16);

        hgemm<<<gProj, 256, GEMM_SMEM>>>(Dz, o16, Dz, owt[l], Dz, y, y16, Dz,
            ob[l], y, Dz, 0);
    }

    // x2 = x + y ; yf16 = LN(x2)  (fused)
    ln_add_kernel<<<M, 256>>>(y, x, x2, yf16, ln2_g, ln2_b);

    hgemm<<<gF1, 256, GEMM_SMEM>>>(Dz, yf16, Dz, w1t, Dz, nullptr, h16, FFNz,
        b1, nullptr, 0, 1);

    hgemm<<<gProj, 256, GEMM_SMEM>>>(FFNz, h16, FFNz, w2t, FFNz, out, nullptr, Dz,
        b2, x2, Dz, 0);
}

// round 10
// speedup vs baseline: 1.8998x; 1.0089x over previous
#include <cuda_runtime.h>
#include <cuda_fp16.h>
#include <cstdint>
#include <math.h>

// Problem constants
#define Bz   4
#define S1z  1024
#define S2z  1024
#define Dz   1024
#define Hz   16
#define DKz  64
#define FFNz 4096

// ---------------- scratch ----------------
__device__ float  g_y   [Bz * S1z * Dz];
__device__ float  g_x2  [Bz * S1z * Dz];
__device__ __half g_y16  [Bz * S1z * Dz];
__device__ __half g_kvn16[Bz * S2z * Dz];
__device__ __half g_q16  [Bz * S1z * Dz];
__device__ __half g_kv16 [(size_t)Bz * S2z * 4096];  // k0|v0|k1|v1, ld=4096
__device__ __half g_o16  [Bz * S1z * Dz];
__device__ __half g_yf16 [Bz * S1z * Dz];
__device__ __half g_h16  [(size_t)Bz * S1z * FFNz];
__device__ __half g_wth  [16 * 1024 * 1024];

// ---------------- helpers ----------------
__device__ __forceinline__ uint32_t smem_u32(const void* p) {
    return (uint32_t)__cvta_generic_to_shared(p);
}
__device__ __forceinline__ void cp16(uint32_t dst, const void* src) {
    asm volatile("cp.async.cg.shared.global [%0], [%1], 16;" :: "r"(dst), "l"(src));
}
__device__ __forceinline__ void mma_f16(float* c, const uint32_t* a, const uint32_t* b) {
    asm volatile("mma.sync.aligned.m16n8k16.row.col.f32.f16.f16.f32 "
                 "{%0,%1,%2,%3},{%4,%5,%6,%7},{%8,%9},{%0,%1,%2,%3};"
                 : "+f"(c[0]), "+f"(c[1]), "+f"(c[2]), "+f"(c[3])
                 : "r"(a[0]), "r"(a[1]), "r"(a[2]), "r"(a[3]), "r"(b[0]), "r"(b[1]));
}
__device__ __forceinline__ void ldsm4(uint32_t* r, uint32_t addr) {
    asm volatile("ldmatrix.sync.aligned.m8n8.x4.shared.b16 {%0,%1,%2,%3}, [%4];"
                 : "=r"(r[0]), "=r"(r[1]), "=r"(r[2]), "=r"(r[3]) : "r"(addr));
}
__device__ __forceinline__ void ldsm4t(uint32_t* r, uint32_t addr) {
    asm volatile("ldmatrix.sync.aligned.m8n8.x4.trans.shared.b16 {%0,%1,%2,%3}, [%4];"
                 : "=r"(r[0]), "=r"(r[1]), "=r"(r[2]), "=r"(r[3]) : "r"(addr));
}
__device__ __forceinline__ uint32_t h2pack(float a, float b) {
    __half2 h = __floats2half2_rn(a, b);
    return *(uint32_t*)&h;
}

// ---------------- fp16 tensor-core GEMM (at mma.sync ceiling — unchanged) ----
#define HSTR 40
#define HSTAGE (256 * HSTR * 2)
#define GEMM_SMEM (3 * HSTAGE)

__global__ void __launch_bounds__(256)
hgemm(int K,
      const __half* __restrict__ A, int lda,
      const __half* __restrict__ Bt, int ldb,
      float* __restrict__ C32, __half* __restrict__ C16, int ldc,
      const float* __restrict__ bias,
      const float* __restrict__ res, int ldres, int relu)
{
    extern __shared__ __align__(16) char smc[];
    int tid = threadIdx.x;
    int bm = blockIdx.y * 128, bn = blockIdx.x * 128;
    int warp = tid >> 5, lane = tid & 31, g = lane >> 2, tg = lane & 3;
    int wn = warp & 1, wm = warp >> 1;

    uint32_t sb = smem_u32(smc);
    const int NT = K / 32;

    auto issue = [&](int t) {
        uint32_t base = sb + (uint32_t)((t % 3) * HSTAGE);
        #pragma unroll
        for (int i = 0; i < 2; i++) {
            int e = tid + i * 256, r = e >> 2, c = (e & 3) * 8;
            cp16(base + (uint32_t)(r * HSTR + c) * 2u,
                 A + (size_t)(bm + r) * lda + t * 32 + c);
        }
        #pragma unroll
        for (int i = 0; i < 2; i++) {
            int e = tid + i * 256, r = e >> 2, c = (e & 3) * 8;
            cp16(base + (uint32_t)((128 + r) * HSTR + c) * 2u,
                 Bt + (size_t)(bn + r) * ldb + t * 32 + c);
        }
        asm volatile("cp.async.commit_group;");
    };

    int q = lane >> 3, rr = lane & 7;
    uint32_t a_off[2][2];
    #pragma unroll
    for (int mi = 0; mi < 2; mi++)
        #pragma unroll
        for (int ks = 0; ks < 2; ks++)
            a_off[mi][ks] = (uint32_t)(((wm*32 + mi*16 + (q&1)*8 + rr) * HSTR
                                        + ks*16 + (q>>1)*8) * 2);
    uint32_t b_off[4][2];
    #pragma unroll
    for (int jp = 0; jp < 4; jp++)
        #pragma unroll
        for (int ks = 0; ks < 2; ks++)
            b_off[jp][ks] = (uint32_t)(((128 + wn*64 + jp*16 + (q>>1)*8 + rr) * HSTR
                                        + ks*16 + (q&1)*8) * 2);

    float acc[2][8][4] = {};

    issue(0);
    if (NT > 1) issue(1);

    for (int t = 0; t < NT; t++) {
        if (t + 1 < NT) asm volatile("cp.async.wait_group 1;");
        else            asm volatile("cp.async.wait_group 0;");
        __syncthreads();
        if (t + 2 < NT) issue(t + 2);

        uint32_t stage = sb + (uint32_t)((t % 3) * HSTAGE);
        #pragma unroll
        for (int ks = 0; ks < 2; ks++) {
            uint32_t a[2][4], b[4][4];
            #pragma unroll
            for (int mi = 0; mi < 2; mi++) ldsm4(a[mi], stage + a_off[mi][ks]);
            #pragma unroll
            for (int jp = 0; jp < 4; jp++) ldsm4(b[jp], stage + b_off[jp][ks]);
            #pragma unroll
            for (int mi = 0; mi < 2; mi++)
                #pragma unroll
                for (int jp = 0; jp < 4; jp++) {
                    mma_f16(acc[mi][jp*2],     a[mi], &b[jp][0]);
                    mma_f16(acc[mi][jp*2 + 1], a[mi], &b[jp][2]);
                }
        }
    }

    #pragma unroll
    for (int mi = 0; mi < 2; mi++) {
        #pragma unroll
        for (int j = 0; j < 8; j++) {
            int m0 = bm + wm*32 + mi*16 + g;
            int n0 = bn + wn*64 + j*8 + 2*tg;
            float v0 = acc[mi][j][0], v1 = acc[mi][j][1];
            float v2 = acc[mi][j][2], v3 = acc[mi][j][3];
            if (bias) {
                float b0 = bias[n0], b1 = bias[n0 + 1];
                v0 += b0; v1 += b1; v2 += b0; v3 += b1;
            }
            if (res) {
                v0 += res[(size_t)m0*ldres + n0];
                v1 += res[(size_t)m0*ldres + n0 + 1];
                v2 += res[(size_t)(m0 + 8)*ldres + n0];
                v3 += res[(size_t)(m0 + 8)*ldres + n0 + 1];
            }
            if (relu) {
                v0 = fmaxf(v0, 0.f); v1 = fmaxf(v1, 0.f);
                v2 = fmaxf(v2, 0.f); v3 = fmaxf(v3, 0.f);
            }
            if (C32) {
                *(float2*)&C32[(size_t)m0*ldc + n0]       = make_float2(v0, v1);
                *(float2*)&C32[(size_t)(m0 + 8)*ldc + n0] = make_float2(v2, v3);
            }
            if (C16) {
                *(__half2*)&C16[(size_t)m0*ldc + n0]       = __floats2half2_rn(v0, v1);
                *(__half2*)&C16[(size_t)(m0 + 8)*ldc + n0] = __floats2half2_rn(v2, v3);
            }
        }
    }
}

// ---------------- transpose + fp32->fp16 -------------------------------------
__global__ void transpose8_kernel(
    const float* s0, __half* d0, const float* s1, __half* d1,
    const float* s2, __half* d2, const float* s3, __half* d3,
    const float* s4, __half* d4, const float* s5, __half* d5,
    const float* s6, __half* d6, const float* s7, __half* d7)
{
    __shared__ float tile[32][33];
    const float* src; __half* dst;
    switch (blockIdx.z) {
        case 0: src = s0; dst = d0; break;
        case 1: src = s1; dst = d1; break;
        case 2: src = s2; dst = d2; break;
        case 3: src = s3; dst = d3; break;
        case 4: src = s4; dst = d4; break;
        case 5: src = s5; dst = d5; break;
        case 6: src = s6; dst = d6; break;
        default: src = s7; dst = d7; break;
    }
    int tx = threadIdx.x, ty = threadIdx.y;
    int c0 = blockIdx.x * 32, r0 = blockIdx.y * 32;
    #pragma unroll
    for (int j = 0; j < 32; j += 8)
        tile[ty + j][tx] = src[(size_t)(r0 + ty + j) * Dz + c0 + tx];
    __syncthreads();
    #pragma unroll
    for (int j = 0; j < 32; j += 8)
        dst[(size_t)(c0 + ty + j) * Dz + r0 + tx] = __float2half_rn(tile[tx][ty + j]);
}

__global__ void transpose_kernel(const float* __restrict__ src, __half* __restrict__ dst,
                                 int R, int C)
{
    __shared__ float tile[32][33];
    int tx = threadIdx.x, ty = threadIdx.y;
    int c0 = blockIdx.x * 32, r0 = blockIdx.y * 32;
    #pragma unroll
    for (int j = 0; j < 32; j += 8)
        tile[ty + j][tx] = src[(size_t)(r0 + ty + j) * C + c0 + tx];
    __syncthreads();
    #pragma unroll
    for (int j = 0; j < 32; j += 8)
        dst[(size_t)(c0 + ty + j) * R + r0 + tx] = __float2half_rn(tile[tx][ty + j]);
}

// ---------------- LayerNorm core ----------------------------------------------
__device__ __forceinline__ void ln_row(float4 v,
                                       float* out32, __half* out16, size_t row, int tid,
                                       const float* __restrict__ g,
                                       const float* __restrict__ bta)
{
    float s = v.x + v.y + v.z + v.w;
    float q = v.x*v.x + v.y*v.y + v.z*v.z + v.w*v.w;
    #pragma unroll
    for (int o = 16; o; o >>= 1) {
        s += __shfl_xor_sync(0xffffffffu, s, o);
        q += __shfl_xor_sync(0xffffffffu, q, o);
    }
    __shared__ float ss[8], qq[8];
    int lane = tid & 31, wid = tid >> 5;
    if (!lane) { ss[wid] = s; qq[wid] = q; }
    __syncthreads();
    if (tid < 32) {
        s = (tid < 8) ? ss[tid] : 0.f;
        q = (tid < 8) ? qq[tid] : 0.f;
        #pragma unroll
        for (int o = 4; o; o >>= 1) {
            s += __shfl_xor_sync(0xffffffffu, s, o);
            q += __shfl_xor_sync(0xffffffffu, q, o);
        }
        if (!tid) { ss[0] = s; qq[0] = q; }
    }
    __syncthreads();
    float mean = ss[0] * (1.f / Dz);
    float var  = qq[0] * (1.f / Dz) - mean * mean;
    float inv  = rsqrtf(var + 1e-5f);
    float4 gv = ((const float4*)g)[tid];
    float4 bv = ((const float4*)bta)[tid];
    float4 o4;
    o4.x = (v.x - mean) * inv * gv.x + bv.x;
    o4.y = (v.y - mean) * inv * gv.y + bv.y;
    o4.z = (v.z - mean) * inv * gv.z + bv.z;
    o4.w = (v.w - mean) * inv * gv.w + bv.w;
    if (out32) ((float4*)(out32 + row * (size_t)Dz))[tid] = o4;
    if (out16) {
        __half2 h0 = __floats2half2_rn(o4.x, o4.y);
        __half2 h1 = __floats2half2_rn(o4.z, o4.w);
        uint2 u = make_uint2(*(uint32_t*)&h0, *(uint32_t*)&h1);
        ((uint2*)(out16 + row * (size_t)Dz))[tid] = u;
    }
}

__global__ void ln_dual_kernel(const float* __restrict__ x, const float* __restrict__ kv,
                               float* __restrict__ y32, __half* __restrict__ y16,
                               __half* __restrict__ kvn16,
                               const float* __restrict__ g, const float* __restrict__ bta)
{
    int tid = threadIdx.x;
    if (blockIdx.x < Bz * S1z) {
        size_t row = blockIdx.x;
        float4 v = ((const float4*)(x + row * (size_t)Dz))[tid];
        ln_row(v, y32, y16, row, tid, g, bta);
    } else {
        size_t row = blockIdx.x - Bz * S1z;
        float4 v = ((const float4*)(kv + row * (size_t)Dz))[tid];
        ln_row(v, nullptr, kvn16, row, tid, g, bta);
    }
}

__global__ void ln_add_kernel(const float* __restrict__ in, const float* __restrict__ add,
                              float* __restrict__ sum32, __half* __restrict__ out16,
                              const float* __restrict__ g, const float* __restrict__ bta)
{
    size_t row = blockIdx.x;
    int tid = threadIdx.x;
    float4 v = ((const float4*)(in + row * (size_t)Dz))[tid];
    float4 a4 = ((const float4*)(add + row * (size_t)Dz))[tid];
    v.x += a4.x; v.y += a4.y; v.z += a4.z; v.w += a4.w;
    ((float4*)(sum32 + row * (size_t)Dz))[tid] = v;
    ln_row(v, nullptr, out16, row, tid, g, bta);
}

// ---------------- fused fp16 flash cross-attention (exp2-domain softmax) -----
#define FSTR 72
#define FLASH_SMEM ((2*64*FSTR + 2*64*FSTR) * 2 + S2z * 4)
#define SCALE2 0.180336880f   // 0.125 * log2(e)

__global__ void __launch_bounds__(256)
flash16_kernel(const __half* __restrict__ Q, const __half* __restrict__ Kg,
               const __half* __restrict__ Vg, int ldkv,
               const int* __restrict__ mask, __half* __restrict__ O16)
{
    extern __shared__ char smc[];
    __half* Ks = (__half*)smc;
    __half* Vs = Ks + 2*64*FSTR;
    float*  Mf = (float*)(Vs + 2*64*FSTR);

    int bh = blockIdx.y;
    int b = bh / Hz, h = bh % Hz;
    int q0 = blockIdx.x * 128;
    int tid = threadIdx.x, warp = tid >> 5, lane = tid & 31, g = lane >> 2, tg = lane & 3;
    int q2 = lane >> 3, rr = lane & 7;

    const __half* Qb = Q  + ((size_t)(b*S1z + q0))*Dz + h*DKz;
    const __half* Kb = Kg + (size_t)b*S2z*ldkv + h*DKz;
    const __half* Vb = Vg + (size_t)b*S2z*ldkv + h*DKz;

    for (int i = tid; i < S2z; i += 256) Mf[i] = mask[(size_t)b*S2z + i] ? 1.f : 0.f;

    uint32_t qa[4][4];
    {
        int ml = warp*16 + g, mh = ml + 8;
        #pragma unroll
        for (int ki = 0; ki < 4; ki++) {
            qa[ki][0] = *(const uint32_t*)&Qb[(size_t)ml*Dz + ki*16 + tg*2];
            qa[ki][1] = *(const uint32_t*)&Qb[(size_t)mh*Dz + ki*16 + tg*2];
            qa[ki][2] = *(const uint32_t*)&Qb[(size_t)ml*Dz + ki*16 + 8 + tg*2];
            qa[ki][3] = *(const uint32_t*)&Qb[(size_t)mh*Dz + ki*16 + 8 + tg*2];
        }
    }

    uint32_t ksb = smem_u32(Ks), vsb = smem_u32(Vs);

    auto issue = [&](int t) {
        int buf = t & 1;
        #pragma unroll
        for (int i = 0; i < 2; i++) {
            int e = tid + i*256, r = e >> 3, c = (e & 7) * 8;
            cp16(ksb + (uint32_t)(buf*64*FSTR + r*FSTR + c)*2u,
                 Kb + (size_t)(t*64 + r)*ldkv + c);
        }
        #pragma unroll
        for (int i = 0; i < 2; i++) {
            int e = tid + i*256, r = e >> 3, c = (e & 7) * 8;
            cp16(vsb + (uint32_t)(buf*64*FSTR + r*FSTR + c)*2u,
                 Vb + (size_t)(t*64 + r)*ldkv + c);
        }
        asm volatile("cp.async.commit_group;");
    };

    uint32_t kb_off[4][4];
    #pragma unroll
    for (int jp = 0; jp < 4; jp++)
        #pragma unroll
        for (int ki = 0; ki < 4; ki++)
            kb_off[jp][ki] = (uint32_t)(((jp*16 + (q2>>1)*8 + rr) * FSTR
                                         + ki*16 + (q2&1)*8) * 2);
    uint32_t vb_off[4][4];
    #pragma unroll
    for (int ki = 0; ki < 4; ki++)
        #pragma unroll
        for (int jp = 0; jp < 4; jp++)
            vb_off[ki][jp] = (uint32_t)(((ki*16 + (q2&1)*8 + rr) * FSTR
                                         + jp*16 + (q2>>1)*8) * 2);

    float s_acc[8][4];
    float o_acc[8][4] = {};
    float m_lo = -INFINITY, m_hi = -INFINITY, l_lo = 0.f, l_hi = 0.f;
    int rl = warp*16 + g, rh = rl + 8;

    issue(0);
    for (int t = 0; t < S2z/64; t++) {
        if (t + 1 < S2z/64) { issue(t + 1); asm volatile("cp.async.wait_group 1;"); }
        else                { asm volatile("cp.async.wait_group 0;"); }
        __syncthreads();
        int buf = t & 1;
        uint32_t kbase = ksb + (uint32_t)(buf*64*FSTR)*2u;
        uint32_t vbase = vsb + (uint32_t)(buf*64*FSTR)*2u;

        // ---- S = Q @ K^T ----
        #pragma unroll
        for (int j = 0; j < 8; j++)
            s_acc[j][0] = s_acc[j][1] = s_acc[j][2] = s_acc[j][3] = 0.f;
        #pragma unroll
        for (int ki = 0; ki < 4; ki++) {
            uint32_t bf[4][4];
            #pragma unroll
            for (int jp = 0; jp < 4; jp++) ldsm4(bf[jp], kbase + kb_off[jp][ki]);
            #pragma unroll
            for (int jp = 0; jp < 4; jp++) {
                mma_f16(s_acc[jp*2],     qa[ki], &bf[jp][0]);
                mma_f16(s_acc[jp*2 + 1], qa[ki], &bf[jp][2]);
            }
        }

        // ---- mask + scale + online softmax in log2 domain ----
        float rmax_lo = -INFINITY, rmax_hi = -INFINITY;
        #pragma unroll
        for (int j = 0; j < 8; j++) {
            int c0 = t*64 + j*8 + 2*tg;
            float mf0 = Mf[c0], mf1 = Mf[c0 + 1];
            s_acc[j][0] = (mf0 != 0.f) ? s_acc[j][0]*SCALE2 : -1e9f;
            s_acc[j][1] = (mf1 != 0.f) ? s_acc[j][1]*SCALE2 : -1e9f;
            s_acc[j][2] = (mf0 != 0.f) ? s_acc[j][2]*SCALE2 : -1e9f;
            s_acc[j][3] = (mf1 != 0.f) ? s_acc[j][3]*SCALE2 : -1e9f;
            rmax_lo = fmaxf(rmax_lo, fmaxf(s_acc[j][0], s_acc[j][1]));
            rmax_hi = fmaxf(rmax_hi, fmaxf(s_acc[j][2], s_acc[j][3]));
        }
        rmax_lo = fmaxf(rmax_lo, __shfl_xor_sync(0xffffffffu, rmax_lo, 1));
        rmax_lo = fmaxf(rmax_lo, __shfl_xor_sync(0xffffffffu, rmax_lo, 2));
        rmax_hi = fmaxf(rmax_hi, __shfl_xor_sync(0xffffffffu, rmax_hi, 1));
        rmax_hi = fmaxf(rmax_hi, __shfl_xor_sync(0xffffffffu, rmax_hi, 2));
        float mn_lo = fmaxf(m_lo, rmax_lo), mn_hi = fmaxf(m_hi, rmax_hi);
        float al_lo = exp2f(m_lo - mn_lo), al_hi = exp2f(m_hi - mn_hi);
        m_lo = mn_lo; m_hi = mn_hi;

        float sum_lo = 0.f, sum_hi = 0.f;
        #pragma unroll
        for (int j = 0; j < 8; j++) {
            s_acc[j][0] = exp2f(s_acc[j][0] - mn_lo);
            s_acc[j][1] = exp2f(s_acc[j][1] - mn_lo);
            s_acc[j][2] = exp2f(s_acc[j][2] - mn_hi);
            s_acc[j][3] = exp2f(s_acc[j][3] - mn_hi);
            sum_lo += s_acc[j][0] + s_acc[j][1];
            sum_hi += s_acc[j][2] + s_acc[j][3];
        }
        sum_lo += __shfl_xor_sync(0xffffffffu, sum_lo, 1);
        sum_lo += __shfl_xor_sync(0xffffffffu, sum_lo, 2);
        sum_hi += __shfl_xor_sync(0xffffffffu, sum_hi, 1);
        sum_hi += __shfl_xor_sync(0xffffffffu, sum_hi, 2);
        l_lo = al_lo*l_lo + sum_lo;
        l_hi = al_hi*l_hi + sum_hi;
        #pragma unroll
        for (int j = 0; j < 8; j++) {
            o_acc[j][0] *= al_lo; o_acc[j][1] *= al_lo;
            o_acc[j][2] *= al_hi; o_acc[j][3] *= al_hi;
        }

        // ---- O += P @ V (P A-frags direct from registers) ----
        #pragma unroll
        for (int ki = 0; ki < 4; ki++) {
            uint32_t pa[4];
            pa[0] = h2pack(s_acc[2*ki    ][0], s_acc[2*ki    ][1]);
            pa[1] = h2pack(s_acc[2*ki    ][2], s_acc[2*ki    ][3]);
            pa[2] = h2pack(s_acc[2*ki + 1][0], s_acc[2*ki + 1][1]);
            pa[3] = h2pack(s_acc[2*ki + 1][2], s_acc[2*ki + 1][3]);
            #pragma unroll
            for (int jp = 0; jp < 4; jp++) {
                uint32_t vb[4];
                ldsm4t(vb, vbase + vb_off[ki][jp]);
                mma_f16(o_acc[jp*2],     pa, &vb[0]);
                mma_f16(o_acc[jp*2 + 1], pa, &vb[2]);
            }
        }
        __syncthreads();
    }

    float il_lo = 1.f / l_lo, il_hi = 1.f / l_hi;
    __half* Ob = O16 + ((size_t)(b*S1z + q0))*Dz + h*DKz;
    #pragma unroll
    for (int j = 0; j < 8; j++) {
        int c = j*8 + 2*tg;
        *(__half2*)&Ob[(size_t)rl*Dz + c] =
            __floats2half2_rn(o_acc[j][0]*il_lo, o_acc[j][1]*il_lo);
        *(__half2*)&Ob[(size_t)rh*Dz + c] =
            __floats2half2_rn(o_acc[j][2]*il_hi, o_acc[j][3]*il_hi);
    }
}

// ---------------- host orchestration ----------------
extern "C" void kernel_launch(void* const* d_in, const int* in_sizes, int n_in,
                              void* d_out, int out_size)
{
    const float* x     = (const float*)d_in[0];
    const float* kv    = (const float*)d_in[1];
    const int*   mask  = (const int*)  d_in[2];
    const float* ln1_g = (const float*)d_in[3];
    const float* ln1_b = (const float*)d_in[4];
    const float* qw[2] = { (const float*)d_in[5],  (const float*)d_in[10] };
    const float* kw[2] = { (const float*)d_in[6],  (const float*)d_in[11] };
    const float* vw[2] = { (const float*)d_in[7],  (const float*)d_in[12] };
    const float* ow[2] = { (const float*)d_in[8],  (const float*)d_in[13] };
    const float* ob[2] = { (const float*)d_in[9],  (const float*)d_in[14] };
    const float* ln2_g = (const float*)d_in[15];
    const float* ln2_b = (const float*)d_in[16];
    const float* w1    = (const float*)d_in[17];
    const float* b1    = (const float*)d_in[18];
    const float* w2    = (const float*)d_in[19];
    const float* b2    = (const float*)d_in[20];
    float* out = (float*)d_out;

    float *y, *x2;
    __half *y16, *kvn16, *q16, *kv16, *o16, *yf16, *h16, *wth;
    cudaGetSymbolAddress((void**)&y,     g_y);
    cudaGetSymbolAddress((void**)&x2,    g_x2);
    cudaGetSymbolAddress((void**)&y16,   g_y16);
    cudaGetSymbolAddress((void**)&kvn16, g_kvn16);
    cudaGetSymbolAddress((void**)&q16,   g_q16);
    cudaGetSymbolAddress((void**)&kv16,  g_kv16);
    cudaGetSymbolAddress((void**)&o16,   g_o16);
    cudaGetSymbolAddress((void**)&yf16,  g_yf16);
    cudaGetSymbolAddress((void**)&h16,   g_h16);
    cudaGetSymbolAddress((void**)&wth,   g_wth);

    cudaFuncSetAttribute(flash16_kernel,
        cudaFuncAttributeMaxDynamicSharedMemorySize, FLASH_SMEM);
    cudaFuncSetAttribute(hgemm,
        cudaFuncAttributeMaxDynamicSharedMemorySize, GEMM_SMEM);

    // one-time side stream + fork/join events (created once; graph-capture
    // turns record/wait into graph edges — no sync, no allocation)
    static cudaStream_t s1 = nullptr;
    static cudaEvent_t evFork = nullptr, evT = nullptr, evLN = nullptr, evKV = nullptr;
    if (!s1) {
        cudaStreamCreateWithFlags(&s1, cudaStreamNonBlocking);
        cudaEventCreateWithFlags(&evFork, cudaEventDisableTiming);
        cudaEventCreateWithFlags(&evT,    cudaEventDisableTiming);
        cudaEventCreateWithFlags(&evLN,   cudaEventDisableTiming);
        cudaEventCreateWithFlags(&evKV,   cudaEventDisableTiming);
    }

    const int M = Bz * S1z;   // 4096
    const size_t MM = 1024 * 1024;

    __half* qwt[2] = { wth + 0*MM, wth + 1*MM };
    __half* owt[2] = { wth + 2*MM, wth + 3*MM };
    __half* kvwt   = wth + 4*MM;
    __half* w1t    = wth + 8*MM;
    __half* w2t    = wth + 12*MM;

    dim3 tb(32, 8);
    dim3 gProj(Dz/128, M/128);
    dim3 gKV(4096/128, M/128);
    dim3 gFlash(S1z/128, Bz*Hz);
    dim3 gF1(FFNz/128, M/128);

    // fork s1 from the capture-origin (legacy) stream
    cudaEventRecord(evFork, 0);
    cudaStreamWaitEvent(s1, evFork, 0);

    // s1: weight transposes (memory-bound) — overlap with LN on legacy stream
    transpose8_kernel<<<dim3(32,32,8), tb, 0, s1>>>(
        qw[0], qwt[0], qw[1], qwt[1], ow[0], owt[0], ow[1], owt[1],
        kw[0], kvwt + 0*MM, vw[0], kvwt + 1*MM, kw[1], kvwt + 2*MM, vw[1], kvwt + 3*MM);
    transpose_kernel<<<dim3(FFNz/32, Dz/32), tb, 0, s1>>>(w1, w1t, Dz, FFNz);
    transpose_kernel<<<dim3(Dz/32, FFNz/32), tb, 0, s1>>>(w2, w2t, FFNz, Dz);

    // legacy: fused LN of x and kv
    ln_dual_kernel<<<Bz * (S1z + S2z), 256>>>(x, kv, y, y16, kvn16, ln1_g, ln1_b);
    cudaEventRecord(evLN, 0);

    // s1: KV mega-GEMM (needs kvwt from s1-order + kvn16 from LN)
    cudaStreamWaitEvent(s1, evLN, 0);
    hgemm<<<gKV, 256, GEMM_SMEM, s1>>>(Dz, kvn16, Dz, kvwt, Dz, nullptr, kv16, 4096,
        nullptr, nullptr, 0, 0);
    cudaEventRecord(evKV, s1);
    cudaEventRecord(evT, s1);   // s1 fully ordered; evT after transposes too

    // legacy: Q-proj l0 (needs qwt[0] from transposes) — runs concurrent with KVproj
    cudaStreamWaitEvent(0, evT, 0);
    hgemm<<<gProj, 256, GEMM_SMEM>>>(Dz, y16, Dz, qwt[0], Dz, nullptr, q16, Dz,
        nullptr, nullptr, 0, 0);

    // join: flash l0 needs kv16
    cudaStreamWaitEvent(0, evKV, 0);

    for (int l = 0; l < 2; l++) {
        if (l == 1) {
            hgemm<<<gProj, 256, GEMM_SMEM>>>(Dz, y16, Dz, qwt[1], Dz, nullptr, q16, Dz,
                nullptr, nullptr, 0, 0);
        }
        flash16_kernel<<<gFlash, 256, FLASH_SMEM>>>(
            q16, kv16 + l*2048, kv16 + l*2048 + 1024, 4096, mask, o16);

        hgemm<<<gProj, 256, GEMM_SMEM>>>(Dz, o16, Dz, owt[l], Dz, y, y16, Dz,
            ob[l], y, Dz, 0);
    }

    // x2 = x + y ; yf16 = LN(x2)
    ln_add_kernel<<<M, 256>>>(y, x, x2, yf16, ln2_g, ln2_b);

    hgemm<<<gF1, 256, GEMM_SMEM>>>(Dz, yf16, Dz, w1t, Dz, nullptr, h16, FFNz,
        b1, nullptr, 0, 1);

    hgemm<<<gProj, 256, GEMM_SMEM>>>(FFNz, h16, FFNz, w2t, FFNz, out, nullptr, Dz,
        b2, x2, Dz, 0);
}

// round 11
// speedup vs baseline: 2.0112x; 1.0587x over previous
#include <cuda_runtime.h>
#include <cuda_fp16.h>
#include <cstdint>
#include <math.h>

// Problem constants
#define Bz   4
#define S1z  1024
#define S2z  1024
#define Dz   1024
#define Hz   16
#define DKz  64
#define FFNz 4096

#define MROWS (Bz * S1z)        // 4096
#define HROWS (MROWS / 2)       // 2048 rows per half (2 batches)

// ---------------- scratch ----------------
__device__ float  g_y   [Bz * S1z * Dz];
__device__ float  g_x2  [Bz * S1z * Dz];
__device__ __half g_y16  [Bz * S1z * Dz];
__device__ __half g_kvn16[Bz * S2z * Dz];
__device__ __half g_q16  [Bz * S1z * Dz];
__device__ __half g_kv16 [(size_t)Bz * S2z * 4096];  // k0|v0|k1|v1, ld=4096
__device__ __half g_o16  [Bz * S1z * Dz];
__device__ __half g_yf16 [Bz * S1z * Dz];
__device__ __half g_h16  [(size_t)Bz * S1z * FFNz];
__device__ __half g_wth  [16 * 1024 * 1024];

// ---------------- helpers ----------------
__device__ __forceinline__ uint32_t smem_u32(const void* p) {
    return (uint32_t)__cvta_generic_to_shared(p);
}
__device__ __forceinline__ void cp16(uint32_t dst, const void* src) {
    asm volatile("cp.async.cg.shared.global [%0], [%1], 16;" :: "r"(dst), "l"(src));
}
__device__ __forceinline__ void mma_f16(float* c, const uint32_t* a, const uint32_t* b) {
    asm volatile("mma.sync.aligned.m16n8k16.row.col.f32.f16.f16.f32 "
                 "{%0,%1,%2,%3},{%4,%5,%6,%7},{%8,%9},{%0,%1,%2,%3};"
                 : "+f"(c[0]), "+f"(c[1]), "+f"(c[2]), "+f"(c[3])
                 : "r"(a[0]), "r"(a[1]), "r"(a[2]), "r"(a[3]), "r"(b[0]), "r"(b[1]));
}
__device__ __forceinline__ void ldsm4(uint32_t* r, uint32_t addr) {
    asm volatile("ldmatrix.sync.aligned.m8n8.x4.shared.b16 {%0,%1,%2,%3}, [%4];"
                 : "=r"(r[0]), "=r"(r[1]), "=r"(r[2]), "=r"(r[3]) : "r"(addr));
}
__device__ __forceinline__ void ldsm4t(uint32_t* r, uint32_t addr) {
    asm volatile("ldmatrix.sync.aligned.m8n8.x4.trans.shared.b16 {%0,%1,%2,%3}, [%4];"
                 : "=r"(r[0]), "=r"(r[1]), "=r"(r[2]), "=r"(r[3]) : "r"(addr));
}
__device__ __forceinline__ uint32_t h2pack(float a, float b) {
    __half2 h = __floats2half2_rn(a, b);
    return *(uint32_t*)&h;
}

// ---------------- fp16 tensor-core GEMM (at mma.sync ceiling — unchanged) ----
#define HSTR 40
#define HSTAGE (256 * HSTR * 2)
#define GEMM_SMEM (3 * HSTAGE)

__global__ void __launch_bounds__(256)
hgemm(int K,
      const __half* __restrict__ A, int lda,
      const __half* __restrict__ Bt, int ldb,
      float* __restrict__ C32, __half* __restrict__ C16, int ldc,
      const float* __restrict__ bias,
      const float* __restrict__ res, int ldres, int relu)
{
    extern __shared__ __align__(16) char smc[];
    int tid = threadIdx.x;
    int bm = blockIdx.y * 128, bn = blockIdx.x * 128;
    int warp = tid >> 5, lane = tid & 31, g = lane >> 2, tg = lane & 3;
    int wn = warp & 1, wm = warp >> 1;

    uint32_t sb = smem_u32(smc);
    const int NT = K / 32;

    auto issue = [&](int t) {
        uint32_t base = sb + (uint32_t)((t % 3) * HSTAGE);
        #pragma unroll
        for (int i = 0; i < 2; i++) {
            int e = tid + i * 256, r = e >> 2, c = (e & 3) * 8;
            cp16(base + (uint32_t)(r * HSTR + c) * 2u,
                 A + (size_t)(bm + r) * lda + t * 32 + c);
        }
        #pragma unroll
        for (int i = 0; i < 2; i++) {
            int e = tid + i * 256, r = e >> 2, c = (e & 3) * 8;
            cp16(base + (uint32_t)((128 + r) * HSTR + c) * 2u,
                 Bt + (size_t)(bn + r) * ldb + t * 32 + c);
        }
        asm volatile("cp.async.commit_group;");
    };

    int q = lane >> 3, rr = lane & 7;
    uint32_t a_off[2][2];
    #pragma unroll
    for (int mi = 0; mi < 2; mi++)
        #pragma unroll
        for (int ks = 0; ks < 2; ks++)
            a_off[mi][ks] = (uint32_t)(((wm*32 + mi*16 + (q&1)*8 + rr) * HSTR
                                        + ks*16 + (q>>1)*8) * 2);
    uint32_t b_off[4][2];
    #pragma unroll
    for (int jp = 0; jp < 4; jp++)
        #pragma unroll
        for (int ks = 0; ks < 2; ks++)
            b_off[jp][ks] = (uint32_t)(((128 + wn*64 + jp*16 + (q>>1)*8 + rr) * HSTR
                                        + ks*16 + (q&1)*8) * 2);

    float acc[2][8][4] = {};

    issue(0);
    if (NT > 1) issue(1);

    for (int t = 0; t < NT; t++) {
        if (t + 1 < NT) asm volatile("cp.async.wait_group 1;");
        else            asm volatile("cp.async.wait_group 0;");
        __syncthreads();
        if (t + 2 < NT) issue(t + 2);

        uint32_t stage = sb + (uint32_t)((t % 3) * HSTAGE);
        #pragma unroll
        for (int ks = 0; ks < 2; ks++) {
            uint32_t a[2][4], b[4][4];
            #pragma unroll
            for (int mi = 0; mi < 2; mi++) ldsm4(a[mi], stage + a_off[mi][ks]);
            #pragma unroll
            for (int jp = 0; jp < 4; jp++) ldsm4(b[jp], stage + b_off[jp][ks]);
            #pragma unroll
            for (int mi = 0; mi < 2; mi++)
                #pragma unroll
                for (int jp = 0; jp < 4; jp++) {
                    mma_f16(acc[mi][jp*2],     a[mi], &b[jp][0]);
                    mma_f16(acc[mi][jp*2 + 1], a[mi], &b[jp][2]);
                }
        }
    }

    #pragma unroll
    for (int mi = 0; mi < 2; mi++) {
        #pragma unroll
        for (int j = 0; j < 8; j++) {
            int m0 = bm + wm*32 + mi*16 + g;
            int n0 = bn + wn*64 + j*8 + 2*tg;
            float v0 = acc[mi][j][0], v1 = acc[mi][j][1];
            float v2 = acc[mi][j][2], v3 = acc[mi][j][3];
            if (bias) {
                float b0 = bias[n0], b1 = bias[n0 + 1];
                v0 += b0; v1 += b1; v2 += b0; v3 += b1;
            }
            if (res) {
                v0 += res[(size_t)m0*ldres + n0];
                v1 += res[(size_t)m0*ldres + n0 + 1];
                v2 += res[(size_t)(m0 + 8)*ldres + n0];
                v3 += res[(size_t)(m0 + 8)*ldres + n0 + 1];
            }
            if (relu) {
                v0 = fmaxf(v0, 0.f); v1 = fmaxf(v1, 0.f);
                v2 = fmaxf(v2, 0.f); v3 = fmaxf(v3, 0.f);
            }
            if (C32) {
                *(float2*)&C32[(size_t)m0*ldc + n0]       = make_float2(v0, v1);
                *(float2*)&C32[(size_t)(m0 + 8)*ldc + n0] = make_float2(v2, v3);
            }
            if (C16) {
                *(__half2*)&C16[(size_t)m0*ldc + n0]       = __floats2half2_rn(v0, v1);
                *(__half2*)&C16[(size_t)(m0 + 8)*ldc + n0] = __floats2half2_rn(v2, v3);
            }
        }
    }
}

// ---------------- transpose + fp32->fp16 -------------------------------------
__global__ void transpose8_kernel(
    const float* s0, __half* d0, const float* s1, __half* d1,
    const float* s2, __half* d2, const float* s3, __half* d3,
    const float* s4, __half* d4, const float* s5, __half* d5,
    const float* s6, __half* d6, const float* s7, __half* d7)
{
    __shared__ float tile[32][33];
    const float* src; __half* dst;
    switch (blockIdx.z) {
        case 0: src = s0; dst = d0; break;
        case 1: src = s1; dst = d1; break;
        case 2: src = s2; dst = d2; break;
        case 3: src = s3; dst = d3; break;
        case 4: src = s4; dst = d4; break;
        case 5: src = s5; dst = d5; break;
        case 6: src = s6; dst = d6; break;
        default: src = s7; dst = d7; break;
    }
    int tx = threadIdx.x, ty = threadIdx.y;
    int c0 = blockIdx.x * 32, r0 = blockIdx.y * 32;
    #pragma unroll
    for (int j = 0; j < 32; j += 8)
        tile[ty + j][tx] = src[(size_t)(r0 + ty + j) * Dz + c0 + tx];
    __syncthreads();
    #pragma unroll
    for (int j = 0; j < 32; j += 8)
        dst[(size_t)(c0 + ty + j) * Dz + r0 + tx] = __float2half_rn(tile[tx][ty + j]);
}

__global__ void transpose_kernel(const float* __restrict__ src, __half* __restrict__ dst,
                                 int R, int C)
{
    __shared__ float tile[32][33];
    int tx = threadIdx.x, ty = threadIdx.y;
    int c0 = blockIdx.x * 32, r0 = blockIdx.y * 32;
    #pragma unroll
    for (int j = 0; j < 32; j += 8)
        tile[ty + j][tx] = src[(size_t)(r0 + ty + j) * C + c0 + tx];
    __syncthreads();
    #pragma unroll
    for (int j = 0; j < 32; j += 8)
        dst[(size_t)(c0 + ty + j) * R + r0 + tx] = __float2half_rn(tile[tx][ty + j]);
}

// ---------------- LayerNorm core ----------------------------------------------
__device__ __forceinline__ void ln_row(float4 v,
                                       float* out32, __half* out16, size_t row, int tid,
                                       const float* __restrict__ g,
                                       const float* __restrict__ bta)
{
    float s = v.x + v.y + v.z + v.w;
    float q = v.x*v.x + v.y*v.y + v.z*v.z + v.w*v.w;
    #pragma unroll
    for (int o = 16; o; o >>= 1) {
        s += __shfl_xor_sync(0xffffffffu, s, o);
        q += __shfl_xor_sync(0xffffffffu, q, o);
    }
    __shared__ float ss[8], qq[8];
    int lane = tid & 31, wid = tid >> 5;
    if (!lane) { ss[wid] = s; qq[wid] = q; }
    __syncthreads();
    if (tid < 32) {
        s = (tid < 8) ? ss[tid] : 0.f;
        q = (tid < 8) ? qq[tid] : 0.f;
        #pragma unroll
        for (int o = 4; o; o >>= 1) {
            s += __shfl_xor_sync(0xffffffffu, s, o);
            q += __shfl_xor_sync(0xffffffffu, q, o);
        }
        if (!tid) { ss[0] = s; qq[0] = q; }
    }
    __syncthreads();
    float mean = ss[0] * (1.f / Dz);
    float var  = qq[0] * (1.f / Dz) - mean * mean;
    float inv  = rsqrtf(var + 1e-5f);
    float4 gv = ((const float4*)g)[tid];
    float4 bv = ((const float4*)bta)[tid];
    float4 o4;
    o4.x = (v.x - mean) * inv * gv.x + bv.x;
    o4.y = (v.y - mean) * inv * gv.y + bv.y;
    o4.z = (v.z - mean) * inv * gv.z + bv.z;
    o4.w = (v.w - mean) * inv * gv.w + bv.w;
    if (out32) ((float4*)(out32 + row * (size_t)Dz))[tid] = o4;
    if (out16) {
        __half2 h0 = __floats2half2_rn(o4.x, o4.y);
        __half2 h1 = __floats2half2_rn(o4.z, o4.w);
        uint2 u = make_uint2(*(uint32_t*)&h0, *(uint32_t*)&h1);
        ((uint2*)(out16 + row * (size_t)Dz))[tid] = u;
    }
}

// LN over n1 rows of x (-> y32,y16) and n2 rows of kv (-> kvn16); pointers pre-offset
__global__ void ln_dual_kernel(const float* __restrict__ x, const float* __restrict__ kv,
                               float* __restrict__ y32, __half* __restrict__ y16,
                               __half* __restrict__ kvn16, int n1,
                               const float* __restrict__ g, const float* __restrict__ bta)
{
    int tid = threadIdx.x;
    if ((int)blockIdx.x < n1) {
        size_t row = blockIdx.x;
        float4 v = ((const float4*)(x + row * (size_t)Dz))[tid];
        ln_row(v, y32, y16, row, tid, g, bta);
    } else {
        size_t row = blockIdx.x - n1;
        float4 v = ((const float4*)(kv + row * (size_t)Dz))[tid];
        ln_row(v, nullptr, kvn16, row, tid, g, bta);
    }
}

__global__ void ln_add_kernel(const float* __restrict__ in, const float* __restrict__ add,
                              float* __restrict__ sum32, __half* __restrict__ out16,
                              const float* __restrict__ g, const float* __restrict__ bta)
{
    size_t row = blockIdx.x;
    int tid = threadIdx.x;
    float4 v = ((const float4*)(in + row * (size_t)Dz))[tid];
    float4 a4 = ((const float4*)(add + row * (size_t)Dz))[tid];
    v.x += a4.x; v.y += a4.y; v.z += a4.z; v.w += a4.w;
    ((float4*)(sum32 + row * (size_t)Dz))[tid] = v;
    ln_row(v, nullptr, out16, row, tid, g, bta);
}

// ---------------- fused fp16 flash cross-attention (exp2 softmax) ------------
#define FSTR 72
#define FLASH_SMEM ((2*64*FSTR + 2*64*FSTR) * 2 + S2z * 4)
#define SCALE2 0.180336880f   // 0.125 * log2(e)

__global__ void __launch_bounds__(256)
flash16_kernel(const __half* __restrict__ Q, const __half* __restrict__ Kg,
               const __half* __restrict__ Vg, int ldkv,
               const int* __restrict__ mask, __half* __restrict__ O16)
{
    extern __shared__ char smc[];
    __half* Ks = (__half*)smc;
    __half* Vs = Ks + 2*64*FSTR;
    float*  Mf = (float*)(Vs + 2*64*FSTR);

    int bh = blockIdx.y;
    int b = bh / Hz, h = bh % Hz;     // b is local to the (pre-offset) pointers
    int q0 = blockIdx.x * 128;
    int tid = threadIdx.x, warp = tid >> 5, lane = tid & 31, g = lane >> 2, tg = lane & 3;
    int q2 = lane >> 3, rr = lane & 7;

    const __half* Qb = Q  + ((size_t)(b*S1z + q0))*Dz + h*DKz;
    const __half* Kb = Kg + (size_t)b*S2z*ldkv + h*DKz;
    const __half* Vb = Vg + (size_t)b*S2z*ldkv + h*DKz;

    for (int i = tid; i < S2z; i += 256) Mf[i] = mask[(size_t)b*S2z + i] ? 1.f : 0.f;

    uint32_t qa[4][4];
    {
        int ml = warp*16 + g, mh = ml + 8;
        #pragma unroll
        for (int ki = 0; ki < 4; ki++) {
            qa[ki][0] = *(const uint32_t*)&Qb[(size_t)ml*Dz + ki*16 + tg*2];
            qa[ki][1] = *(const uint32_t*)&Qb[(size_t)mh*Dz + ki*16 + tg*2];
            qa[ki][2] = *(const uint32_t*)&Qb[(size_t)ml*Dz + ki*16 + 8 + tg*2];
            qa[ki][3] = *(const uint32_t*)&Qb[(size_t)mh*Dz + ki*16 + 8 + tg*2];
        }
    }

    uint32_t ksb = smem_u32(Ks), vsb = smem_u32(Vs);

    auto issue = [&](int t) {
        int buf = t & 1;
        #pragma unroll
        for (int i = 0; i < 2; i++) {
            int e = tid + i*256, r = e >> 3, c = (e & 7) * 8;
            cp16(ksb + (uint32_t)(buf*64*FSTR + r*FSTR + c)*2u,
                 Kb + (size_t)(t*64 + r)*ldkv + c);
        }
        #pragma unroll
        for (int i = 0; i < 2; i++) {
            int e = tid + i*256, r = e >> 3, c = (e & 7) * 8;
            cp16(vsb + (uint32_t)(buf*64*FSTR + r*FSTR + c)*2u,
                 Vb + (size_t)(t*64 + r)*ldkv + c);
        }
        asm volatile("cp.async.commit_group;");
    };

    uint32_t kb_off[4][4];
    #pragma unroll
    for (int jp = 0; jp < 4; jp++)
        #pragma unroll
        for (int ki = 0; ki < 4; ki++)
            kb_off[jp][ki] = (uint32_t)(((jp*16 + (q2>>1)*8 + rr) * FSTR
                                         + ki*16 + (q2&1)*8) * 2);
    uint32_t vb_off[4][4];
    #pragma unroll
    for (int ki = 0; ki < 4; ki++)
        #pragma unroll
        for (int jp = 0; jp < 4; jp++)
            vb_off[ki][jp] = (uint32_t)(((ki*16 + (q2&1)*8 + rr) * FSTR
                                         + jp*16 + (q2>>1)*8) * 2);

    float s_acc[8][4];
    float o_acc[8][4] = {};
    float m_lo = -INFINITY, m_hi = -INFINITY, l_lo = 0.f, l_hi = 0.f;
    int rl = warp*16 + g, rh = rl + 8;

    issue(0);
    for (int t = 0; t < S2z/64; t++) {
        if (t + 1 < S2z/64) { issue(t + 1); asm volatile("cp.async.wait_group 1;"); }
        else                { asm volatile("cp.async.wait_group 0;"); }
        __syncthreads();
        int buf = t & 1;
        uint32_t kbase = ksb + (uint32_t)(buf*64*FSTR)*2u;
        uint32_t vbase = vsb + (uint32_t)(buf*64*FSTR)*2u;

        #pragma unroll
        for (int j = 0; j < 8; j++)
            s_acc[j][0] = s_acc[j][1] = s_acc[j][2] = s_acc[j][3] = 0.f;
        #pragma unroll
        for (int ki = 0; ki < 4; ki++) {
            uint32_t bf[4][4];
            #pragma unroll
            for (int jp = 0; jp < 4; jp++) ldsm4(bf[jp], kbase + kb_off[jp][ki]);
            #pragma unroll
            for (int jp = 0; jp < 4; jp++) {
                mma_f16(s_acc[jp*2],     qa[ki], &bf[jp][0]);
                mma_f16(s_acc[jp*2 + 1], qa[ki], &bf[jp][2]);
            }
        }

        float rmax_lo = -INFINITY, rmax_hi = -INFINITY;
        #pragma unroll
        for (int j = 0; j < 8; j++) {
            int c0 = t*64 + j*8 + 2*tg;
            float mf0 = Mf[c0], mf1 = Mf[c0 + 1];
            s_acc[j][0] = (mf0 != 0.f) ? s_acc[j][0]*SCALE2 : -1e9f;
            s_acc[j][1] = (mf1 != 0.f) ? s_acc[j][1]*SCALE2 : -1e9f;
            s_acc[j][2] = (mf0 != 0.f) ? s_acc[j][2]*SCALE2 : -1e9f;
            s_acc[j][3] = (mf1 != 0.f) ? s_acc[j][3]*SCALE2 : -1e9f;
            rmax_lo = fmaxf(rmax_lo, fmaxf(s_acc[j][0], s_acc[j][1]));
            rmax_hi = fmaxf(rmax_hi, fmaxf(s_acc[j][2], s_acc[j][3]));
        }
        rmax_lo = fmaxf(rmax_lo, __shfl_xor_sync(0xffffffffu, rmax_lo, 1));
        rmax_lo = fmaxf(rmax_lo, __shfl_xor_sync(0xffffffffu, rmax_lo, 2));
        rmax_hi = fmaxf(rmax_hi, __shfl_xor_sync(0xffffffffu, rmax_hi, 1));
        rmax_hi = fmaxf(rmax_hi, __shfl_xor_sync(0xffffffffu, rmax_hi, 2));
        float mn_lo = fmaxf(m_lo, rmax_lo), mn_hi = fmaxf(m_hi, rmax_hi);
        float al_lo = exp2f(m_lo - mn_lo), al_hi = exp2f(m_hi - mn_hi);
        m_lo = mn_lo; m_hi = mn_hi;

        float sum_lo = 0.f, sum_hi = 0.f;
        #pragma unroll
        for (int j = 0; j < 8; j++) {
            s_acc[j][0] = exp2f(s_acc[j][0] - mn_lo);
            s_acc[j][1] = exp2f(s_acc[j][1] - mn_lo);
            s_acc[j][2] = exp2f(s_acc[j][2] - mn_hi);
            s_acc[j][3] = exp2f(s_acc[j][3] - mn_hi);
            sum_lo += s_acc[j][0] + s_acc[j][1];
            sum_hi += s_acc[j][2] + s_acc[j][3];
        }
        sum_lo += __shfl_xor_sync(0xffffffffu, sum_lo, 1);
        sum_lo += __shfl_xor_sync(0xffffffffu, sum_lo, 2);
        sum_hi += __shfl_xor_sync(0xffffffffu, sum_hi, 1);
        sum_hi += __shfl_xor_sync(0xffffffffu, sum_hi, 2);
        l_lo = al_lo*l_lo + sum_lo;
        l_hi = al_hi*l_hi + sum_hi;
        #pragma unroll
        for (int j = 0; j < 8; j++) {
            o_acc[j][0] *= al_lo; o_acc[j][1] *= al_lo;
            o_acc[j][2] *= al_hi; o_acc[j][3] *= al_hi;
        }

        #pragma unroll
        for (int ki = 0; ki < 4; ki++) {
            uint32_t pa[4];
            pa[0] = h2pack(s_acc[2*ki    ][0], s_acc[2*ki    ][1]);
            pa[1] = h2pack(s_acc[2*ki    ][2], s_acc[2*ki    ][3]);
            pa[2] = h2pack(s_acc[2*ki + 1][0], s_acc[2*ki + 1][1]);
            pa[3] = h2pack(s_acc[2*ki + 1][2], s_acc[2*ki + 1][3]);
            #pragma unroll
            for (int jp = 0; jp < 4; jp++) {
                uint32_t vb[4];
                ldsm4t(vb, vbase + vb_off[ki][jp]);
                mma_f16(o_acc[jp*2],     pa, &vb[0]);
                mma_f16(o_acc[jp*2 + 1], pa, &vb[2]);
            }
        }
        __syncthreads();
    }

    float il_lo = 1.f / l_lo, il_hi = 1.f / l_hi;
    __half* Ob = O16 + ((size_t)(b*S1z + q0))*Dz + h*DKz;
    #pragma unroll
    for (int j = 0; j < 8; j++) {
        int c = j*8 + 2*tg;
        *(__half2*)&Ob[(size_t)rl*Dz + c] =
            __floats2half2_rn(o_acc[j][0]*il_lo, o_acc[j][1]*il_lo);
        *(__half2*)&Ob[(size_t)rh*Dz + c] =
            __floats2half2_rn(o_acc[j][2]*il_hi, o_acc[j][3]*il_hi);
    }
}

// ---------------- host orchestration ----------------
extern "C" void kernel_launch(void* const* d_in, const int* in_sizes, int n_in,
                              void* d_out, int out_size)
{
    const float* x     = (const float*)d_in[0];
    const float* kv    = (const float*)d_in[1];
    const int*   mask  = (const int*)  d_in[2];
    const float* ln1_g = (const float*)d_in[3];
    const float* ln1_b = (const float*)d_in[4];
    const float* qw[2] = { (const float*)d_in[5],  (const float*)d_in[10] };
    const float* kw[2] = { (const float*)d_in[6],  (const float*)d_in[11] };
    const float* vw[2] = { (const float*)d_in[7],  (const float*)d_in[12] };
    const float* ow[2] = { (const float*)d_in[8],  (const float*)d_in[13] };
    const float* ob[2] = { (const float*)d_in[9],  (const float*)d_in[14] };
    const float* ln2_g = (const float*)d_in[15];
    const float* ln2_b = (const float*)d_in[16];
    const float* w1    = (const float*)d_in[17];
    const float* b1    = (const float*)d_in[18];
    const float* w2    = (const float*)d_in[19];
    const float* b2    = (const float*)d_in[20];
    float* out = (float*)d_out;

    float *y, *x2;
    __half *y16, *kvn16, *q16, *kv16, *o16, *yf16, *h16, *wth;
    cudaGetSymbolAddress((void**)&y,     g_y);
    cudaGetSymbolAddress((void**)&x2,    g_x2);
    cudaGetSymbolAddress((void**)&y16,   g_y16);
    cudaGetSymbolAddress((void**)&kvn16, g_kvn16);
    cudaGetSymbolAddress((void**)&q16,   g_q16);
    cudaGetSymbolAddress((void**)&kv16,  g_kv16);
    cudaGetSymbolAddress((void**)&o16,   g_o16);
    cudaGetSymbolAddress((void**)&yf16,  g_yf16);
    cudaGetSymbolAddress((void**)&h16,   g_h16);
    cudaGetSymbolAddress((void**)&wth,   g_wth);

    cudaFuncSetAttribute(flash16_kernel,
        cudaFuncAttributeMaxDynamicSharedMemorySize, FLASH_SMEM);
    cudaFuncSetAttribute(hgemm,
        cudaFuncAttributeMaxDynamicSharedMemorySize, GEMM_SMEM);

    // one-time side stream + events (record/wait become graph edges)
    static cudaStream_t s1 = nullptr;
    static cudaEvent_t evFork = nullptr, evW = nullptr, evEnd = nullptr;
    if (!s1) {
        cudaStreamCreateWithFlags(&s1, cudaStreamNonBlocking);
        cudaEventCreateWithFlags(&evFork, cudaEventDisableTiming);
        cudaEventCreateWithFlags(&evW,    cudaEventDisableTiming);
        cudaEventCreateWithFlags(&evEnd,  cudaEventDisableTiming);
    }

    const size_t MM = 1024 * 1024;
    __half* qwt[2] = { wth + 0*MM, wth + 1*MM };
    __half* owt[2] = { wth + 2*MM, wth + 3*MM };
    __half* kvwt   = wth + 4*MM;
    __half* w1t    = wth + 8*MM;
    __half* w2t    = wth + 12*MM;

    dim3 tb(32, 8);
    // half-sized grids
    dim3 gProjH(Dz/128, HROWS/128);     // (8, 16)
    dim3 gKVH(4096/128, HROWS/128);     // (32, 16)
    dim3 gFlashH(S1z/128, 2*Hz);        // (8, 32) — 2 batches per half
    dim3 gF1H(FFNz/128, HROWS/128);     // (32, 16)

    // fork: s1 waits on capture-origin stream
    cudaEventRecord(evFork, 0);
    cudaStreamWaitEvent(s1, evFork, 0);

    // legacy(0): weight transposes (shared by both halves)
    transpose8_kernel<<<dim3(32,32,8), tb>>>(
        qw[0], qwt[0], qw[1], qwt[1], ow[0], owt[0], ow[1], owt[1],
        kw[0], kvwt + 0*MM, vw[0], kvwt + 1*MM, kw[1], kvwt + 2*MM, vw[1], kvwt + 3*MM);
    transpose_kernel<<<dim3(FFNz/32, Dz/32), tb>>>(w1, w1t, Dz, FFNz);
    transpose_kernel<<<dim3(Dz/32, FFNz/32), tb>>>(w2, w2t, FFNz, Dz);
    cudaEventRecord(evW, 0);
    cudaStreamWaitEvent(s1, evW, 0);

    // per-half pipelines: half 0 -> stream 0, half 1 -> s1
    for (int hh = 0; hh < 2; hh++) {
        cudaStream_t st = (hh == 0) ? (cudaStream_t)0 : s1;
        size_t R  = (size_t)hh * HROWS;          // row offset (2048)
        const float* xh  = x  + R * Dz;
        const float* kvh = kv + R * Dz;
        const int*   mh  = mask + R;             // R rows = 2 batches * S2z ints? no:
        // mask is [B, S2]; 2 batches per half -> offset = hh * 2 * S2z
        mh = mask + (size_t)hh * 2 * S2z;

        float*  yh    = y     + R * Dz;
        float*  x2h   = x2    + R * Dz;
        __half* y16h  = y16   + R * Dz;
        __half* kvnh  = kvn16 + R * Dz;
        __half* q16h  = q16   + R * Dz;
        __half* kv16h = kv16  + R * 4096;
        __half* o16h  = o16   + R * Dz;
        __half* yf16h = yf16  + R * Dz;
        __half* h16h  = h16   + R * FFNz;
        float*  outh  = out   + R * Dz;

        // LN of x-half and kv-half
        ln_dual_kernel<<<2 * HROWS, 256, 0, st>>>(
            xh, kvh, yh, y16h, kvnh, HROWS, ln1_g, ln1_b);

        // KV mega-GEMM (both layers' K,V for this half's batches)
        hgemm<<<gKVH, 256, GEMM_SMEM, st>>>(Dz, kvnh, Dz, kvwt, Dz,
            nullptr, kv16h, 4096, nullptr, nullptr, 0, 0);

        for (int l = 0; l < 2; l++) {
            hgemm<<<gProjH, 256, GEMM_SMEM, st>>>(Dz, y16h, Dz, qwt[l], Dz,
                nullptr, q16h, Dz, nullptr, nullptr, 0, 0);

            flash16_kernel<<<gFlashH, 256, FLASH_SMEM, st>>>(
                q16h, kv16h + l*2048, kv16h + l*2048 + 1024, 4096, mh, o16h);

            hgemm<<<gProjH, 256, GEMM_SMEM, st>>>(Dz, o16h, Dz, owt[l], Dz,
                yh, y16h, Dz, ob[l], yh, Dz, 0);
        }

        // x2 = x + y ; yf16 = LN(x2)
        ln_add_kernel<<<HROWS, 256, 0, st>>>(yh, xh, x2h, yf16h, ln2_g, ln2_b);

        // FFN
        hgemm<<<gF1H, 256, GEMM_SMEM, st>>>(Dz, yf16h, Dz, w1t, Dz,
            nullptr, h16h, FFNz, b1, nullptr, 0, 1);
        hgemm<<<gProjH, 256, GEMM_SMEM, st>>>(FFNz, h16h, FFNz, w2t, FFNz,
            outh, nullptr, Dz, b2, x2h, Dz, 0);
    }

    // join: capture-origin stream waits for s1's half
    cudaEventRecord(evEnd, s1);
    cudaStreamWaitEvent(0, evEnd, 0);
}